// round 8
// baseline (speedup 1.0000x reference)
#include <cuda_runtime.h>

// ---------------- problem dims (compile-time) ----------------
#define L_SEQ   1024
#define D_MODEL 512
#define N_B     2
#define N_H     8
#define N_P     4
#define INV_TEMP 0.125f     // 1/sqrt(64)
#define LN_EPS   1e-6f

#define OUT_ELEMS  (N_P * N_B * L_SEQ * D_MODEL)     // 4,194,304
#define ATTN_ELEMS (N_B * N_H * L_SEQ * L_SEQ)       // 16,777,216

// ---------------- device scratch (no allocations allowed) ----------------
__device__ float g_qn[N_B * L_SEQ * D_MODEL];
__device__ float g_qh[N_B * L_SEQ * D_MODEL];
__device__ float g_kh[N_B * L_SEQ * D_MODEL];
__device__ float g_vh[N_B * L_SEQ * D_MODEL];
__device__ float g_ho[N_P * N_B * L_SEQ * D_MODEL];
__device__ float g_attn_fallback[ATTN_ELEMS];

// ---------------- packed f32x2 helpers (sm_103a FFMA2 path) ----------------
__device__ __forceinline__ unsigned long long pk2(float x, float y) {
    unsigned long long r;
    asm("mov.b64 %0, {%1, %2};" : "=l"(r) : "f"(x), "f"(y));
    return r;
}
__device__ __forceinline__ void fma2(unsigned long long& c, unsigned long long a, unsigned long long b) {
    asm("fma.rn.f32x2 %0, %1, %2, %0;" : "+l"(c) : "l"(a), "l"(b));
}
__device__ __forceinline__ float2 upk2(unsigned long long v) {
    float2 r;
    asm("mov.b64 {%0, %1}, %2;" : "=f"(r.x), "=f"(r.y) : "l"(v));
    return r;
}

// ---------------- LayerNorm over last dim (512) ----------------
__global__ __launch_bounds__(128)
void ln_kernel(const float* __restrict__ q, const float* __restrict__ g,
               const float* __restrict__ b, float* __restrict__ out) {
    int row = blockIdx.x;
    const float* x = q + (size_t)row * D_MODEL;
    int tid = threadIdx.x;
    float4 v = reinterpret_cast<const float4*>(x)[tid];
    float s  = v.x + v.y + v.z + v.w;
    float s2 = v.x * v.x + v.y * v.y + v.z * v.z + v.w * v.w;
    #pragma unroll
    for (int o = 16; o > 0; o >>= 1) {
        s  += __shfl_xor_sync(0xffffffffu, s,  o);
        s2 += __shfl_xor_sync(0xffffffffu, s2, o);
    }
    __shared__ float shs[4], shs2[4];
    __shared__ float sh_mu, sh_rs;
    int w = tid >> 5;
    if ((tid & 31) == 0) { shs[w] = s; shs2[w] = s2; }
    __syncthreads();
    if (tid == 0) {
        float S  = shs[0] + shs[1] + shs[2] + shs[3];
        float S2 = shs2[0] + shs2[1] + shs2[2] + shs2[3];
        float mu = S * (1.0f / D_MODEL);
        float var = S2 * (1.0f / D_MODEL) - mu * mu;
        sh_mu = mu;
        sh_rs = rsqrtf(var + LN_EPS);
    }
    __syncthreads();
    float mu = sh_mu, rs = sh_rs;
    float4 gv = reinterpret_cast<const float4*>(g)[tid];
    float4 bv = reinterpret_cast<const float4*>(b)[tid];
    float4 o;
    o.x = (v.x - mu) * rs * gv.x + bv.x;
    o.y = (v.y - mu) * rs * gv.y + bv.y;
    o.z = (v.z - mu) * rs * gv.z + bv.z;
    o.w = (v.w - mu) * rs * gv.w + bv.w;
    reinterpret_cast<float4*>(out + (size_t)row * D_MODEL)[tid] = o;
}

// ---------------- 128x64-tile SGEMM: C[m,n] = sum_k A[m,k]*W[n,k] ----------------
// Key layout trick: A is stored in smem duplicate-packed ((a,a) as u64), B is
// read as ulonglong2 (natural pairs). Inner loop is mov-free: 16 FFMA2 + 5 LDS.
#define GM_PROJ 0
#define GM_ATTN 2
#define GM_FC   3
#define KT 32

template <int MODE>
__global__ __launch_bounds__(256)
void gemm128(const float* __restrict__ A0, const float* __restrict__ W0,
             float* __restrict__ C0, int K, int lda, int ldb, int ldc,
             const float* __restrict__ bias, const float* __restrict__ resid,
             const float* __restrict__ A1, const float* __restrict__ W1, float* __restrict__ C1,
             const float* __restrict__ A2, const float* __restrict__ W2, float* __restrict__ C2) {
    __shared__ unsigned long long As2[KT][128];   // dup-packed [k][m], 32KB
    __shared__ float Bs[KT][64];                  // [k][n], 8KB

    int tid = threadIdx.x;
    int tx = tid & 15, ty = tid >> 4;
    int m0 = blockIdx.y << 7, n0 = blockIdx.x << 6;

    const float* A = A0; const float* W = W0; float* C = C0;
    float scale = 1.0f;
    if (MODE == GM_PROJ) {
        int z = blockIdx.z;
        if (z == 0)      { scale = INV_TEMP; }
        else if (z == 1) { A = A1; W = W1; C = C1; }
        else             { A = A2; W = W2; C = C2; }
    }
    if (MODE == GM_ATTN) {
        int z = blockIdx.z;
        size_t off = (size_t)(z >> 3) * L_SEQ * D_MODEL + (size_t)(z & 7) * 64;
        A += off; W += off; C += (size_t)z * L_SEQ * L_SEQ;
    }

    int alr = tid >> 1, ak0 = (tid & 1) << 4;   // A: row, k-base {0,16}; 128B/row coalesced
    int blr = tid >> 2, bk0 = (tid & 3) << 3;   // B: row, k-base {0,8,16,24}
    const float* arow = A + (size_t)(m0 + alr) * lda + ak0;
    const float* brow = W + (size_t)(n0 + blr) * ldb + bk0;

    unsigned long long acc[8][2];
    #pragma unroll
    for (int i = 0; i < 8; i++) { acc[i][0] = 0ull; acc[i][1] = 0ull; }

    for (int k0 = 0; k0 < K; k0 += KT) {
        float4 a[4], bv[2];
        #pragma unroll
        for (int j = 0; j < 4; j++) a[j]  = *reinterpret_cast<const float4*>(arow + k0 + 4 * j);
        #pragma unroll
        for (int j = 0; j < 2; j++) bv[j] = *reinterpret_cast<const float4*>(brow + k0 + 4 * j);
        if (k0) __syncthreads();
        #pragma unroll
        for (int j = 0; j < 4; j++) {
            As2[ak0 + 4 * j + 0][alr] = pk2(a[j].x, a[j].x);
            As2[ak0 + 4 * j + 1][alr] = pk2(a[j].y, a[j].y);
            As2[ak0 + 4 * j + 2][alr] = pk2(a[j].z, a[j].z);
            As2[ak0 + 4 * j + 3][alr] = pk2(a[j].w, a[j].w);
        }
        #pragma unroll
        for (int j = 0; j < 2; j++) {
            Bs[bk0 + 4 * j + 0][blr] = bv[j].x;
            Bs[bk0 + 4 * j + 1][blr] = bv[j].y;
            Bs[bk0 + 4 * j + 2][blr] = bv[j].z;
            Bs[bk0 + 4 * j + 3][blr] = bv[j].w;
        }
        __syncthreads();
        #pragma unroll 16
        for (int kk = 0; kk < KT; kk++) {
            ulonglong2 a01 = *reinterpret_cast<const ulonglong2*>(&As2[kk][(ty << 3) + 0]);
            ulonglong2 a23 = *reinterpret_cast<const ulonglong2*>(&As2[kk][(ty << 3) + 2]);
            ulonglong2 a45 = *reinterpret_cast<const ulonglong2*>(&As2[kk][(ty << 3) + 4]);
            ulonglong2 a67 = *reinterpret_cast<const ulonglong2*>(&As2[kk][(ty << 3) + 6]);
            ulonglong2 bb  = *reinterpret_cast<const ulonglong2*>(&Bs[kk][tx << 2]);
            fma2(acc[0][0], a01.x, bb.x); fma2(acc[0][1], a01.x, bb.y);
            fma2(acc[1][0], a01.y, bb.x); fma2(acc[1][1], a01.y, bb.y);
            fma2(acc[2][0], a23.x, bb.x); fma2(acc[2][1], a23.x, bb.y);
            fma2(acc[3][0], a23.y, bb.x); fma2(acc[3][1], a23.y, bb.y);
            fma2(acc[4][0], a45.x, bb.x); fma2(acc[4][1], a45.x, bb.y);
            fma2(acc[5][0], a45.y, bb.x); fma2(acc[5][1], a45.y, bb.y);
            fma2(acc[6][0], a67.x, bb.x); fma2(acc[6][1], a67.x, bb.y);
            fma2(acc[7][0], a67.y, bb.x); fma2(acc[7][1], a67.y, bb.y);
        }
    }

    #pragma unroll
    for (int i = 0; i < 8; i++) {
        int row = m0 + (ty << 3) + i;
        int col = n0 + (tx << 2);
        float2 c01 = upk2(acc[i][0]);
        float2 c23 = upk2(acc[i][1]);
        float4 r = make_float4(c01.x, c01.y, c23.x, c23.y);
        if (MODE == GM_PROJ) {
            r.x *= scale; r.y *= scale; r.z *= scale; r.w *= scale;
        }
        if (MODE == GM_FC) {
            float4 bb4 = *reinterpret_cast<const float4*>(bias + col);
            const float* rp = resid + (size_t)(row & (N_B * L_SEQ - 1)) * D_MODEL + col;
            float4 rv = *reinterpret_cast<const float4*>(rp);
            r.x += bb4.x + rv.x; r.y += bb4.y + rv.y;
            r.z += bb4.z + rv.z; r.w += bb4.w + rv.w;
        }
        *reinterpret_cast<float4*>(C + (size_t)row * ldc + col) = r;
    }
}

// ---------------- fused masked softmax + P*V (GEMM-structured) ----------------
// Tile: 128 q-rows x 64 dv, streaming k in 64-chunks. E = mask*exp(s) computed
// once per tile, stored TRANSPOSED + dup-packed in smem; the PV inner loop is
// then identical to the mov-free GEMM inner loop. Z accumulated alongside;
// divide at the end (no max subtraction needed: |s| <= ~6).
#define SM_ES2_BYTES (64 * 128 * 8)                 // 65536
#define SM_VS_BYTES  (64 * 68 * 4)                  // 17408 (pad 68 kills store conflicts)
#define SM_TOTAL     (SM_ES2_BYTES + SM_VS_BYTES + 128 * 4)

__global__ __launch_bounds__(256)
void softmax_pv2(const float* __restrict__ attn, const float* __restrict__ mask,
                 const float* __restrict__ vh, float* __restrict__ ho) {
    extern __shared__ char smem_raw[];
    unsigned long long (*Es2)[128] = reinterpret_cast<unsigned long long (*)[128]>(smem_raw);
    float (*Vs)[68] = reinterpret_cast<float (*)[68]>(smem_raw + SM_ES2_BYTES);
    float* Zs = reinterpret_cast<float*>(smem_raw + SM_ES2_BYTES + SM_VS_BYTES);

    int tid = threadIdx.x;
    int tx = tid & 15, ty = tid >> 4;
    int elr = tid >> 1, ek0 = (tid & 1) << 5;   // E: row 0..127, k-base {0,32}
    int vlr = tid >> 2, vc0 = (tid & 3) << 4;   // V: row 0..63, col-base {0,16,32,48}

    int q0 = blockIdx.x << 7;
    int bh = blockIdx.y, b = bh >> 3, h = bh & 7;
    int p = blockIdx.z;

    const float* Sp = attn + (size_t)bh * L_SEQ * L_SEQ + (size_t)(q0 + elr) * L_SEQ + ek0;
    const float* Mp = mask + (size_t)p * L_SEQ * L_SEQ + (size_t)(q0 + elr) * L_SEQ + ek0;
    const float* Vp = vh + (size_t)b * L_SEQ * D_MODEL + (size_t)h * 64 + vc0;

    unsigned long long acc[8][2];
    #pragma unroll
    for (int i = 0; i < 8; i++) { acc[i][0] = 0ull; acc[i][1] = 0ull; }
    float zacc = 0.0f;

    for (int kt = 0; kt < 16; kt++) {
        int kb = kt << 6;
        if (kt) __syncthreads();   // previous inner loop done before overwrite
        // V tile -> smem (direct copy, [k][d])
        #pragma unroll
        for (int j = 0; j < 4; j++) {
            float4 vv = *reinterpret_cast<const float4*>(Vp + (size_t)(kb + vlr) * D_MODEL + 4 * j);
            *reinterpret_cast<float4*>(&Vs[vlr][vc0 + 4 * j]) = vv;
        }
        // E tile: exp + mask, transposed dup-packed store, running row-sum
        #pragma unroll
        for (int j = 0; j < 8; j++) {
            float4 s4 = *reinterpret_cast<const float4*>(Sp + kb + 4 * j);
            float4 m4 = *reinterpret_cast<const float4*>(Mp + kb + 4 * j);
            float ex = m4.x * __expf(s4.x);
            float ey = m4.y * __expf(s4.y);
            float ez = m4.z * __expf(s4.z);
            float ew = m4.w * __expf(s4.w);
            zacc += ex + ey + ez + ew;
            int k = ek0 + 4 * j;
            Es2[k + 0][elr] = pk2(ex, ex);
            Es2[k + 1][elr] = pk2(ey, ey);
            Es2[k + 2][elr] = pk2(ez, ez);
            Es2[k + 3][elr] = pk2(ew, ew);
        }
        __syncthreads();
        #pragma unroll 8
        for (int kk = 0; kk < 64; kk++) {
            ulonglong2 a01 = *reinterpret_cast<const ulonglong2*>(&Es2[kk][(ty << 3) + 0]);
            ulonglong2 a23 = *reinterpret_cast<const ulonglong2*>(&Es2[kk][(ty << 3) + 2]);
            ulonglong2 a45 = *reinterpret_cast<const ulonglong2*>(&Es2[kk][(ty << 3) + 4]);
            ulonglong2 a67 = *reinterpret_cast<const ulonglong2*>(&Es2[kk][(ty << 3) + 6]);
            ulonglong2 bb  = *reinterpret_cast<const ulonglong2*>(&Vs[kk][tx << 2]);
            fma2(acc[0][0], a01.x, bb.x); fma2(acc[0][1], a01.x, bb.y);
            fma2(acc[1][0], a01.y, bb.x); fma2(acc[1][1], a01.y, bb.y);
            fma2(acc[2][0], a23.x, bb.x); fma2(acc[2][1], a23.x, bb.y);
            fma2(acc[3][0], a23.y, bb.x); fma2(acc[3][1], a23.y, bb.y);
            fma2(acc[4][0], a45.x, bb.x); fma2(acc[4][1], a45.x, bb.y);
            fma2(acc[5][0], a45.y, bb.x); fma2(acc[5][1], a45.y, bb.y);
            fma2(acc[6][0], a67.x, bb.x); fma2(acc[6][1], a67.x, bb.y);
            fma2(acc[7][0], a67.y, bb.x); fma2(acc[7][1], a67.y, bb.y);
        }
    }

    // finalize row sums (pair of threads shares one E row)
    zacc += __shfl_xor_sync(0xffffffffu, zacc, 1);
    if ((tid & 1) == 0) Zs[elr] = zacc;
    __syncthreads();

    float* hop = ho + ((size_t)((p * N_B + b) * L_SEQ + q0)) * D_MODEL + (size_t)h * 64;
    #pragma unroll
    for (int i = 0; i < 8; i++) {
        int row = (ty << 3) + i;
        float zi = 1.0f / Zs[row];
        float2 c01 = upk2(acc[i][0]);
        float2 c23 = upk2(acc[i][1]);
        float4 r = make_float4(c01.x * zi, c01.y * zi, c23.x * zi, c23.y * zi);
        *reinterpret_cast<float4*>(hop + (size_t)row * D_MODEL + (tx << 2)) = r;
    }
}

// ---------------- launch ----------------
extern "C" void kernel_launch(void* const* d_in, const int* in_sizes, int n_in,
                              void* d_out, int out_size) {
    const float* q    = (const float*)d_in[0];
    const float* k    = (const float*)d_in[1];
    const float* v    = (const float*)d_in[2];
    const float* mask = (const float*)d_in[3];
    const float* w_q  = (const float*)d_in[4];
    const float* w_k  = (const float*)d_in[5];
    const float* w_v  = (const float*)d_in[6];
    const float* fc_w = (const float*)d_in[7];
    const float* fc_b = (const float*)d_in[8];
    const float* ln_g = (const float*)d_in[9];
    const float* ln_b = (const float*)d_in[10];

    float* out = (float*)d_out;

    float *qn, *qh, *kh, *vh, *ho, *attn_fb;
    cudaGetSymbolAddress((void**)&qn, g_qn);
    cudaGetSymbolAddress((void**)&qh, g_qh);
    cudaGetSymbolAddress((void**)&kh, g_kh);
    cudaGetSymbolAddress((void**)&vh, g_vh);
    cudaGetSymbolAddress((void**)&ho, g_ho);
    cudaGetSymbolAddress((void**)&attn_fb, g_attn_fallback);

    float* attn_out = (out_size >= OUT_ELEMS + ATTN_ELEMS) ? out + OUT_ELEMS : attn_fb;

    cudaFuncSetAttribute(softmax_pv2, cudaFuncAttributeMaxDynamicSharedMemorySize, SM_TOTAL);

    // 1. pre-LN on q
    ln_kernel<<<N_B * L_SEQ, 128>>>(q, ln_g, ln_b, qn);

    // 2. all three projections in ONE launch (z selects); q-proj folds 1/sqrt(dk)
    dim3 gproj(D_MODEL / 64, (N_B * L_SEQ) / 128, 3);         // (8, 16, 3) = 384 blocks
    gemm128<GM_PROJ><<<gproj, 256>>>(qn, w_q, qh, D_MODEL, D_MODEL, D_MODEL, D_MODEL,
                                     nullptr, nullptr, k, w_k, kh, v, w_v, vh);

    // 3. attention scores: per (b,h): S[1024,1024] = qh_bh * kh_bh^T
    dim3 gattn(L_SEQ / 64, L_SEQ / 128, N_B * N_H);           // (16, 8, 16) = 2048 blocks
    gemm128<GM_ATTN><<<gattn, 256>>>(qh, kh, attn_out, 64, D_MODEL, D_MODEL, L_SEQ,
                                     nullptr, nullptr, nullptr, nullptr, nullptr,
                                     nullptr, nullptr, nullptr);

    // 4. fused masked softmax + PV for all P masks
    dim3 gsm(L_SEQ / 128, N_B * N_H, N_P);                    // (8, 16, 4) = 512 blocks
    softmax_pv2<<<gsm, 256, SM_TOTAL>>>(attn_out, mask, vh, ho);

    // 5. FC + bias + residual -> out [P,B,L,D]
    dim3 gfc(D_MODEL / 64, (N_P * N_B * L_SEQ) / 128, 1);     // (8, 64) = 512 blocks
    gemm128<GM_FC><<<gfc, 256>>>(ho, fc_w, out, D_MODEL, D_MODEL, D_MODEL, D_MODEL,
                                 fc_b, q, nullptr, nullptr, nullptr,
                                 nullptr, nullptr, nullptr);
}

// round 13
// speedup vs baseline: 1.9928x; 1.9928x over previous
#include <cuda_runtime.h>

// ---------------- problem dims ----------------
#define L_SEQ   1024
#define LL      (L_SEQ * L_SEQ)
#define D_MODEL 512
#define N_B     2
#define N_H     8
#define N_P     4
#define INV_TEMP 0.125f
#define LN_EPS   1e-6f

#define OUT_ELEMS  (N_P * N_B * L_SEQ * D_MODEL)
#define ATTN_ELEMS (N_B * N_H * L_SEQ * L_SEQ)

// ---------------- device scratch ----------------
__device__ float g_qn[N_B * L_SEQ * D_MODEL];
__device__ float g_qh[N_B * L_SEQ * D_MODEL];
__device__ float g_kh[N_B * L_SEQ * D_MODEL];
__device__ float g_vh[N_B * L_SEQ * D_MODEL];
__device__ float g_ho[N_P * N_B * L_SEQ * D_MODEL];
__device__ float g_attn_fallback[ATTN_ELEMS];
__device__ float g_exp[ATTN_ELEMS];                 // exp(S), written by QK epilogue

// ---------------- packed f32x2 helpers ----------------
__device__ __forceinline__ unsigned long long pk2(float x, float y) {
    unsigned long long r;
    asm("mov.b64 %0, {%1, %2};" : "=l"(r) : "f"(x), "f"(y));
    return r;
}
__device__ __forceinline__ void fma2(unsigned long long& c, unsigned long long a, unsigned long long b) {
    asm("fma.rn.f32x2 %0, %1, %2, %0;" : "+l"(c) : "l"(a), "l"(b));
}
__device__ __forceinline__ float2 upk2(unsigned long long v) {
    float2 r;
    asm("mov.b64 {%0, %1}, %2;" : "=f"(r.x), "=f"(r.y) : "l"(v));
    return r;
}

// ---------------- LayerNorm ----------------
__global__ __launch_bounds__(128)
void ln_kernel(const float* __restrict__ q, const float* __restrict__ g,
               const float* __restrict__ b, float* __restrict__ out) {
    int row = blockIdx.x;
    const float* x = q + (size_t)row * D_MODEL;
    int tid = threadIdx.x;
    float4 v = reinterpret_cast<const float4*>(x)[tid];
    float s  = v.x + v.y + v.z + v.w;
    float s2 = v.x * v.x + v.y * v.y + v.z * v.z + v.w * v.w;
    #pragma unroll
    for (int o = 16; o > 0; o >>= 1) {
        s  += __shfl_xor_sync(0xffffffffu, s,  o);
        s2 += __shfl_xor_sync(0xffffffffu, s2, o);
    }
    __shared__ float shs[4], shs2[4];
    __shared__ float sh_mu, sh_rs;
    int w = tid >> 5;
    if ((tid & 31) == 0) { shs[w] = s; shs2[w] = s2; }
    __syncthreads();
    if (tid == 0) {
        float S  = shs[0] + shs[1] + shs[2] + shs[3];
        float S2 = shs2[0] + shs2[1] + shs2[2] + shs2[3];
        float mu = S * (1.0f / D_MODEL);
        float var = S2 * (1.0f / D_MODEL) - mu * mu;
        sh_mu = mu;
        sh_rs = rsqrtf(var + LN_EPS);
    }
    __syncthreads();
    float mu = sh_mu, rs = sh_rs;
    float4 gv = reinterpret_cast<const float4*>(g)[tid];
    float4 bv = reinterpret_cast<const float4*>(b)[tid];
    float4 o;
    o.x = (v.x - mu) * rs * gv.x + bv.x;
    o.y = (v.y - mu) * rs * gv.y + bv.y;
    o.z = (v.z - mu) * rs * gv.z + bv.z;
    o.w = (v.w - mu) * rs * gv.w + bv.w;
    reinterpret_cast<float4*>(out + (size_t)row * D_MODEL)[tid] = o;
}

// ---------------- 128x128 SGEMM, 8x8/thread, plain smem + mov-dup ----------------
// C[m,n] = sum_k A[m,k] * W[n,k]
#define GM_PROJ 0
#define GM_ATTN 2
#define GM_FC   3
#define KT 32

template <int MODE>
__global__ __launch_bounds__(256, 2)
void gemm128(const float* __restrict__ A0, const float* __restrict__ W0,
             float* __restrict__ C0, int K, int lda, int ldb, int ldc,
             const float* __restrict__ bias, const float* __restrict__ resid,
             float* __restrict__ E0,
             const float* __restrict__ A1, const float* __restrict__ W1, float* __restrict__ C1,
             const float* __restrict__ A2, const float* __restrict__ W2, float* __restrict__ C2) {
    __shared__ float As[KT][132];   // [k][m], pad 4
    __shared__ float Bs[KT][132];   // [k][n], pad 4

    int tid = threadIdx.x;
    int tx = tid & 15, ty = tid >> 4;
    int m0 = blockIdx.y << 7, n0 = blockIdx.x << 7;

    const float* A = A0; const float* W = W0; float* C = C0; float* E = E0;
    float scale = 1.0f;
    if (MODE == GM_PROJ) {
        int z = blockIdx.z;
        if (z == 0)      { scale = INV_TEMP; }
        else if (z == 1) { A = A1; W = W1; C = C1; }
        else             { A = A2; W = W2; C = C2; }
    }
    if (MODE == GM_ATTN) {
        int z = blockIdx.z;
        size_t off = (size_t)(z >> 3) * L_SEQ * D_MODEL + (size_t)(z & 7) * 64;
        A += off; W += off;
        C += (size_t)z * LL;
        E += (size_t)z * LL;
    }

    int alr = tid >> 1, ak0 = (tid & 1) << 4;    // 128 rows, 16-k halves
    const float* arow = A + (size_t)(m0 + alr) * lda + ak0;
    const float* brow = W + (size_t)(n0 + alr) * ldb + ak0;

    unsigned long long acc[8][4];
    #pragma unroll
    for (int i = 0; i < 8; i++)
        #pragma unroll
        for (int j = 0; j < 4; j++) acc[i][j] = 0ull;

    for (int k0 = 0; k0 < K; k0 += KT) {
        float4 a[4], bv[4];
        #pragma unroll
        for (int j = 0; j < 4; j++) {
            a[j]  = *reinterpret_cast<const float4*>(arow + k0 + 4 * j);
            bv[j] = *reinterpret_cast<const float4*>(brow + k0 + 4 * j);
        }
        if (k0) __syncthreads();
        #pragma unroll
        for (int j = 0; j < 4; j++) {
            As[ak0 + 4 * j + 0][alr] = a[j].x;
            As[ak0 + 4 * j + 1][alr] = a[j].y;
            As[ak0 + 4 * j + 2][alr] = a[j].z;
            As[ak0 + 4 * j + 3][alr] = a[j].w;
            Bs[ak0 + 4 * j + 0][alr] = bv[j].x;
            Bs[ak0 + 4 * j + 1][alr] = bv[j].y;
            Bs[ak0 + 4 * j + 2][alr] = bv[j].z;
            Bs[ak0 + 4 * j + 3][alr] = bv[j].w;
        }
        __syncthreads();
        #pragma unroll 16
        for (int kk = 0; kk < KT; kk++) {
            float4 x0 = *reinterpret_cast<const float4*>(&As[kk][ty << 3]);
            float4 x1 = *reinterpret_cast<const float4*>(&As[kk][(ty << 3) + 4]);
            ulonglong2 u0 = *reinterpret_cast<const ulonglong2*>(&Bs[kk][tx << 3]);
            ulonglong2 u1 = *reinterpret_cast<const ulonglong2*>(&Bs[kk][(tx << 3) + 4]);
            unsigned long long d;
            d = pk2(x0.x, x0.x); fma2(acc[0][0], d, u0.x); fma2(acc[0][1], d, u0.y); fma2(acc[0][2], d, u1.x); fma2(acc[0][3], d, u1.y);
            d = pk2(x0.y, x0.y); fma2(acc[1][0], d, u0.x); fma2(acc[1][1], d, u0.y); fma2(acc[1][2], d, u1.x); fma2(acc[1][3], d, u1.y);
            d = pk2(x0.z, x0.z); fma2(acc[2][0], d, u0.x); fma2(acc[2][1], d, u0.y); fma2(acc[2][2], d, u1.x); fma2(acc[2][3], d, u1.y);
            d = pk2(x0.w, x0.w); fma2(acc[3][0], d, u0.x); fma2(acc[3][1], d, u0.y); fma2(acc[3][2], d, u1.x); fma2(acc[3][3], d, u1.y);
            d = pk2(x1.x, x1.x); fma2(acc[4][0], d, u0.x); fma2(acc[4][1], d, u0.y); fma2(acc[4][2], d, u1.x); fma2(acc[4][3], d, u1.y);
            d = pk2(x1.y, x1.y); fma2(acc[5][0], d, u0.x); fma2(acc[5][1], d, u0.y); fma2(acc[5][2], d, u1.x); fma2(acc[5][3], d, u1.y);
            d = pk2(x1.z, x1.z); fma2(acc[6][0], d, u0.x); fma2(acc[6][1], d, u0.y); fma2(acc[6][2], d, u1.x); fma2(acc[6][3], d, u1.y);
            d = pk2(x1.w, x1.w); fma2(acc[7][0], d, u0.x); fma2(acc[7][1], d, u0.y); fma2(acc[7][2], d, u1.x); fma2(acc[7][3], d, u1.y);
        }
    }

    #pragma unroll
    for (int i = 0; i < 8; i++) {
        int row = m0 + (ty << 3) + i;
        int col = n0 + (tx << 3);
        float2 c0 = upk2(acc[i][0]);
        float2 c1 = upk2(acc[i][1]);
        float2 c2 = upk2(acc[i][2]);
        float2 c3 = upk2(acc[i][3]);
        float4 r0 = make_float4(c0.x, c0.y, c1.x, c1.y);
        float4 r1 = make_float4(c2.x, c2.y, c3.x, c3.y);
        if (MODE == GM_PROJ) {
            r0.x *= scale; r0.y *= scale; r0.z *= scale; r0.w *= scale;
            r1.x *= scale; r1.y *= scale; r1.z *= scale; r1.w *= scale;
        }
        if (MODE == GM_FC) {
            float4 b0 = *reinterpret_cast<const float4*>(bias + col);
            float4 b1 = *reinterpret_cast<const float4*>(bias + col + 4);
            const float* rp = resid + (size_t)(row & (N_B * L_SEQ - 1)) * D_MODEL + col;
            float4 v0 = *reinterpret_cast<const float4*>(rp);
            float4 v1 = *reinterpret_cast<const float4*>(rp + 4);
            r0.x += b0.x + v0.x; r0.y += b0.y + v0.y; r0.z += b0.z + v0.z; r0.w += b0.w + v0.w;
            r1.x += b1.x + v1.x; r1.y += b1.y + v1.y; r1.z += b1.z + v1.z; r1.w += b1.w + v1.w;
        }
        float* cp = C + (size_t)row * ldc + col;
        *reinterpret_cast<float4*>(cp)     = r0;
        *reinterpret_cast<float4*>(cp + 4) = r1;
        if (MODE == GM_ATTN) {
            float4 e0 = make_float4(__expf(r0.x), __expf(r0.y), __expf(r0.z), __expf(r0.w));
            float4 e1 = make_float4(__expf(r1.x), __expf(r1.y), __expf(r1.z), __expf(r1.w));
            float* ep = E + (size_t)row * ldc + col;
            *reinterpret_cast<float4*>(ep)     = e0;
            *reinterpret_cast<float4*>(ep + 4) = e1;
        }
    }
}

// ---------------- fused masked-softmax + PV ----------------
// tile 128q x 64d, 8x8/thread, 128 threads, 4 blocks/SM.
// Reads precomputed E = exp(S); e = mask*E; O = (e . V) / Z.
// E stored transposed in smem with XOR swizzle col = q ^ ((k>>4)<<2).
#define ES_STRIDE 132
#define VS_STRIDE 68
#define PV_SMEM   ((64 * ES_STRIDE + 64 * VS_STRIDE + 128) * 4)

__global__ __launch_bounds__(128, 4)
void softmax_pv3(const float* __restrict__ Ebuf, const float* __restrict__ mask,
                 const float* __restrict__ vh, float* __restrict__ ho) {
    extern __shared__ float sm[];
    float* Es = sm;
    float* Vs = sm + 64 * ES_STRIDE;
    float* Zs = Vs + 64 * VS_STRIDE;

    int tid = threadIdx.x;
    int tx = tid & 7, ty = tid >> 3;          // ty 0..15 -> 8 q rows each
    int q0 = blockIdx.x << 7;
    int bh = blockIdx.y, b = bh >> 3, h = bh & 7;
    int p = blockIdx.z;

    int eq  = tid >> 2;                        // 0..31 (q row, 4 passes of 32)
    int ek0 = (tid & 3) << 4;                  // k quarter
    int xsw = (tid & 3) << 2;                  // store swizzle = (k>>4)<<2

    const float* Ep = Ebuf + (size_t)bh * LL + (size_t)q0 * L_SEQ;
    const float* Mp = mask + (size_t)p * LL + (size_t)q0 * L_SEQ;
    const float* Vp = vh + (size_t)b * L_SEQ * D_MODEL + (size_t)h * 64;

    int vrow = tid & 63, vcb = (tid >> 6) << 5;

    unsigned long long acc[8][4];
    #pragma unroll
    for (int i = 0; i < 8; i++)
        #pragma unroll
        for (int j = 0; j < 4; j++) acc[i][j] = 0ull;
    float zacc[4] = {0.f, 0.f, 0.f, 0.f};

    for (int kt = 0; kt < 16; kt++) {
        int kb = kt << 6;
        if (kt) __syncthreads();
        // V chunk [64k x 64d] -> smem
        #pragma unroll
        for (int j = 0; j < 8; j++) {
            float4 vv = *reinterpret_cast<const float4*>(
                Vp + (size_t)(kb + vrow) * D_MODEL + vcb + 4 * j);
            *reinterpret_cast<float4*>(&Vs[vrow * VS_STRIDE + vcb + 4 * j]) = vv;
        }
        // E chunk: e = mask * E, transposed swizzled store + running Z
        #pragma unroll
        for (int pass = 0; pass < 4; pass++) {
            int qq = eq + (pass << 5);
            const float* ep = Ep + (size_t)qq * L_SEQ + kb + ek0;
            const float* mp = Mp + (size_t)qq * L_SEQ + kb + ek0;
            int colq = qq ^ xsw;
            #pragma unroll
            for (int j = 0; j < 4; j++) {
                float4 e4 = *reinterpret_cast<const float4*>(ep + 4 * j);
                float4 m4 = *reinterpret_cast<const float4*>(mp + 4 * j);
                float e0 = e4.x * m4.x, e1 = e4.y * m4.y;
                float e2 = e4.z * m4.z, e3 = e4.w * m4.w;
                zacc[pass] += (e0 + e1) + (e2 + e3);
                int kr = ek0 + 4 * j;
                Es[(kr + 0) * ES_STRIDE + colq] = e0;
                Es[(kr + 1) * ES_STRIDE + colq] = e1;
                Es[(kr + 2) * ES_STRIDE + colq] = e2;
                Es[(kr + 3) * ES_STRIDE + colq] = e3;
            }
        }
        __syncthreads();
        // inner GEMM: 4 sub-blocks of 16 k each (swizzle constant per sub-block)
        for (int kk16 = 0; kk16 < 4; kk16++) {
            int x2 = kk16 << 2;
            int ca = (ty << 3) ^ x2;
            int cb = ((ty << 3) + 4) ^ x2;
            int kbase = kk16 << 4;
            #pragma unroll
            for (int k2 = 0; k2 < 16; k2++) {
                int kk = kbase + k2;
                float4 x0 = *reinterpret_cast<const float4*>(&Es[kk * ES_STRIDE + ca]);
                float4 x1 = *reinterpret_cast<const float4*>(&Es[kk * ES_STRIDE + cb]);
                ulonglong2 u0 = *reinterpret_cast<const ulonglong2*>(&Vs[kk * VS_STRIDE + (tx << 3)]);
                ulonglong2 u1 = *reinterpret_cast<const ulonglong2*>(&Vs[kk * VS_STRIDE + (tx << 3) + 4]);
                unsigned long long d;
                d = pk2(x0.x, x0.x); fma2(acc[0][0], d, u0.x); fma2(acc[0][1], d, u0.y); fma2(acc[0][2], d, u1.x); fma2(acc[0][3], d, u1.y);
                d = pk2(x0.y, x0.y); fma2(acc[1][0], d, u0.x); fma2(acc[1][1], d, u0.y); fma2(acc[1][2], d, u1.x); fma2(acc[1][3], d, u1.y);
                d = pk2(x0.z, x0.z); fma2(acc[2][0], d, u0.x); fma2(acc[2][1], d, u0.y); fma2(acc[2][2], d, u1.x); fma2(acc[2][3], d, u1.y);
                d = pk2(x0.w, x0.w); fma2(acc[3][0], d, u0.x); fma2(acc[3][1], d, u0.y); fma2(acc[3][2], d, u1.x); fma2(acc[3][3], d, u1.y);
                d = pk2(x1.x, x1.x); fma2(acc[4][0], d, u0.x); fma2(acc[4][1], d, u0.y); fma2(acc[4][2], d, u1.x); fma2(acc[4][3], d, u1.y);
                d = pk2(x1.y, x1.y); fma2(acc[5][0], d, u0.x); fma2(acc[5][1], d, u0.y); fma2(acc[5][2], d, u1.x); fma2(acc[5][3], d, u1.y);
                d = pk2(x1.z, x1.z); fma2(acc[6][0], d, u0.x); fma2(acc[6][1], d, u0.y); fma2(acc[6][2], d, u1.x); fma2(acc[6][3], d, u1.y);
                d = pk2(x1.w, x1.w); fma2(acc[7][0], d, u0.x); fma2(acc[7][1], d, u0.y); fma2(acc[7][2], d, u1.x); fma2(acc[7][3], d, u1.y);
            }
        }
    }

    // row sums: lanes (tid&3) share a q row per pass
    #pragma unroll
    for (int pass = 0; pass < 4; pass++) {
        float vz = zacc[pass];
        vz += __shfl_xor_sync(0xffffffffu, vz, 1);
        vz += __shfl_xor_sync(0xffffffffu, vz, 2);
        if ((tid & 3) == 0) Zs[eq + (pass << 5)] = vz;
    }
    __syncthreads();

    float* hop = ho + ((size_t)((p * N_B + b) * L_SEQ + q0)) * D_MODEL + (size_t)h * 64;
    #pragma unroll
    for (int i = 0; i < 8; i++) {
        int row = (ty << 3) + i;
        float zi = 1.0f / Zs[row];
        float2 c0 = upk2(acc[i][0]);
        float2 c1 = upk2(acc[i][1]);
        float2 c2 = upk2(acc[i][2]);
        float2 c3 = upk2(acc[i][3]);
        float4 r0 = make_float4(c0.x * zi, c0.y * zi, c1.x * zi, c1.y * zi);
        float4 r1 = make_float4(c2.x * zi, c2.y * zi, c3.x * zi, c3.y * zi);
        float* op = hop + (size_t)row * D_MODEL + (tx << 3);
        *reinterpret_cast<float4*>(op)     = r0;
        *reinterpret_cast<float4*>(op + 4) = r1;
    }
}

// ---------------- launch ----------------
extern "C" void kernel_launch(void* const* d_in, const int* in_sizes, int n_in,
                              void* d_out, int out_size) {
    const float* q    = (const float*)d_in[0];
    const float* k    = (const float*)d_in[1];
    const float* v    = (const float*)d_in[2];
    const float* mask = (const float*)d_in[3];
    const float* w_q  = (const float*)d_in[4];
    const float* w_k  = (const float*)d_in[5];
    const float* w_v  = (const float*)d_in[6];
    const float* fc_w = (const float*)d_in[7];
    const float* fc_b = (const float*)d_in[8];
    const float* ln_g = (const float*)d_in[9];
    const float* ln_b = (const float*)d_in[10];

    float* out = (float*)d_out;

    float *qn, *qh, *kh, *vh, *ho, *attn_fb, *ebuf;
    cudaGetSymbolAddress((void**)&qn, g_qn);
    cudaGetSymbolAddress((void**)&qh, g_qh);
    cudaGetSymbolAddress((void**)&kh, g_kh);
    cudaGetSymbolAddress((void**)&vh, g_vh);
    cudaGetSymbolAddress((void**)&ho, g_ho);
    cudaGetSymbolAddress((void**)&attn_fb, g_attn_fallback);
    cudaGetSymbolAddress((void**)&ebuf, g_exp);

    float* attn_out = (out_size >= OUT_ELEMS + ATTN_ELEMS) ? out + OUT_ELEMS : attn_fb;

    cudaFuncSetAttribute(softmax_pv3, cudaFuncAttributeMaxDynamicSharedMemorySize, PV_SMEM);

    // 1. pre-LN on q
    ln_kernel<<<N_B * L_SEQ, 128>>>(q, ln_g, ln_b, qn);

    // 2. q/k/v projections in one launch (q-proj folds 1/sqrt(dk))
    dim3 gproj(D_MODEL / 128, (N_B * L_SEQ) / 128, 3);        // (4, 16, 3)
    gemm128<GM_PROJ><<<gproj, 256>>>(qn, w_q, qh, D_MODEL, D_MODEL, D_MODEL, D_MODEL,
                                     nullptr, nullptr, nullptr,
                                     k, w_k, kh, v, w_v, vh);

    // 3. scores S = qh.kh^T (written to attn output) + E = exp(S) (scratch)
    dim3 gattn(L_SEQ / 128, L_SEQ / 128, N_B * N_H);          // (8, 8, 16)
    gemm128<GM_ATTN><<<gattn, 256>>>(qh, kh, attn_out, 64, D_MODEL, D_MODEL, L_SEQ,
                                     nullptr, nullptr, ebuf,
                                     nullptr, nullptr, nullptr,
                                     nullptr, nullptr, nullptr);

    // 4. masked softmax + PV for all P masks (reads E, not S)
    dim3 gsm(L_SEQ / 128, N_B * N_H, N_P);                    // (8, 16, 4)
    softmax_pv3<<<gsm, 128, PV_SMEM>>>(ebuf, mask, vh, ho);

    // 5. FC + bias + residual
    dim3 gfc(D_MODEL / 128, (N_P * N_B * L_SEQ) / 128, 1);    // (4, 64)
    gemm128<GM_FC><<<gfc, 256>>>(ho, fc_w, out, D_MODEL, D_MODEL, D_MODEL, D_MODEL,
                                 fc_b, q, nullptr,
                                 nullptr, nullptr, nullptr,
                                 nullptr, nullptr, nullptr);
}

// round 16
// speedup vs baseline: 2.7722x; 1.3911x over previous
#include <cstdint>
#include <cstddef>
#include <cuda_runtime.h>
#include <cuda_bf16.h>

// ---------------- problem dims ----------------
#define L_SEQ   1024
#define LL      (L_SEQ * L_SEQ)
#define D_MODEL 512
#define N_B     2
#define N_H     8
#define N_BH    (N_B * N_H)
#define N_P     4
#define INV_TEMP 0.125f
#define LN_EPS   1e-6f

#define OUT_ELEMS  (N_P * N_B * L_SEQ * D_MODEL)
#define ATTN_ELEMS (N_BH * LL)
#define VT_PLANE   (N_BH * 64 * L_SEQ)

// ---------------- device scratch ----------------
__device__ float g_qn[N_B * L_SEQ * D_MODEL];
__device__ float g_qh[N_B * L_SEQ * D_MODEL];
__device__ float g_kh[N_B * L_SEQ * D_MODEL];
__device__ float g_vh[N_B * L_SEQ * D_MODEL];
__device__ float g_ho[N_P * N_B * L_SEQ * D_MODEL];
__device__ float g_attn_fallback[ATTN_ELEMS];
__device__ unsigned short g_ehi[ATTN_ELEMS];        // bf16 hi of exp(S)
__device__ unsigned short g_elo[ATTN_ELEMS];        // bf16 lo of exp(S)
__device__ unsigned short g_vt[2 * VT_PLANE];       // V^T bf16 hi plane, then lo plane
__device__ unsigned char  g_mb[LL];                 // 4 mask bits packed per (q,k)

// ---------------- packed f32x2 helpers (FFMA2 path) ----------------
__device__ __forceinline__ unsigned long long pk2(float x, float y) {
    unsigned long long r;
    asm("mov.b64 %0, {%1, %2};" : "=l"(r) : "f"(x), "f"(y));
    return r;
}
__device__ __forceinline__ void fma2(unsigned long long& c, unsigned long long a, unsigned long long b) {
    asm("fma.rn.f32x2 %0, %1, %2, %0;" : "+l"(c) : "l"(a), "l"(b));
}
__device__ __forceinline__ float2 upk2(unsigned long long v) {
    float2 r;
    asm("mov.b64 {%0, %1}, %2;" : "=f"(r.x), "=f"(r.y) : "l"(v));
    return r;
}

// ---------------- warp MMA helpers (non-'a' ISA: ldmatrix + mma.sync) ----------------
__device__ __forceinline__ uint32_t smem_u32(const void* p) {
    uint32_t a;
    asm("{ .reg .u64 t; cvta.to.shared.u64 t, %1; cvt.u32.u64 %0, t; }" : "=r"(a) : "l"(p));
    return a;
}
__device__ __forceinline__ void ldm_x4(uint32_t* r, uint32_t addr) {
    asm volatile("ldmatrix.sync.aligned.m8n8.x4.shared.b16 {%0,%1,%2,%3}, [%4];"
                 : "=r"(r[0]), "=r"(r[1]), "=r"(r[2]), "=r"(r[3]) : "r"(addr));
}
__device__ __forceinline__ void mma16816(float* c, const uint32_t* a, const uint32_t* b) {
    asm volatile("mma.sync.aligned.m16n8k16.row.col.f32.bf16.bf16.f32 "
                 "{%0,%1,%2,%3}, {%4,%5,%6,%7}, {%8,%9}, {%0,%1,%2,%3};"
                 : "+f"(c[0]), "+f"(c[1]), "+f"(c[2]), "+f"(c[3])
                 : "r"(a[0]), "r"(a[1]), "r"(a[2]), "r"(a[3]), "r"(b[0]), "r"(b[1]));
}

#define SW128(o) ((o) ^ (((o) >> 3) & 0x70))
#define STS128(a, x, y, z, w) asm volatile("st.shared.v4.b32 [%0], {%1,%2,%3,%4};" :: "r"(a), "r"(x), "r"(y), "r"(z), "r"(w) : "memory")

// ---------------- LayerNorm ----------------
__global__ __launch_bounds__(128)
void ln_kernel(const float* __restrict__ q, const float* __restrict__ g,
               const float* __restrict__ b, float* __restrict__ out) {
    int row = blockIdx.x;
    const float* x = q + (size_t)row * D_MODEL;
    int tid = threadIdx.x;
    float4 v = reinterpret_cast<const float4*>(x)[tid];
    float s  = v.x + v.y + v.z + v.w;
    float s2 = v.x * v.x + v.y * v.y + v.z * v.z + v.w * v.w;
    #pragma unroll
    for (int o = 16; o > 0; o >>= 1) {
        s  += __shfl_xor_sync(0xffffffffu, s,  o);
        s2 += __shfl_xor_sync(0xffffffffu, s2, o);
    }
    __shared__ float shs[4], shs2[4];
    __shared__ float sh_mu, sh_rs;
    int w = tid >> 5;
    if ((tid & 31) == 0) { shs[w] = s; shs2[w] = s2; }
    __syncthreads();
    if (tid == 0) {
        float S  = shs[0] + shs[1] + shs[2] + shs[3];
        float S2 = shs2[0] + shs2[1] + shs2[2] + shs2[3];
        float mu = S * (1.0f / D_MODEL);
        float var = S2 * (1.0f / D_MODEL) - mu * mu;
        sh_mu = mu;
        sh_rs = rsqrtf(var + LN_EPS);
    }
    __syncthreads();
    float mu = sh_mu, rs = sh_rs;
    float4 gv = reinterpret_cast<const float4*>(g)[tid];
    float4 bv = reinterpret_cast<const float4*>(b)[tid];
    float4 o;
    o.x = (v.x - mu) * rs * gv.x + bv.x;
    o.y = (v.y - mu) * rs * gv.y + bv.y;
    o.z = (v.z - mu) * rs * gv.z + bv.z;
    o.w = (v.w - mu) * rs * gv.w + bv.w;
    reinterpret_cast<float4*>(out + (size_t)row * D_MODEL)[tid] = o;
}

// ---------------- mask pack: 4 fp32 masks -> 4 bits/byte ----------------
__global__ __launch_bounds__(256)
void maskpack_kernel(const float* __restrict__ mask, unsigned char* __restrict__ mb) {
    int i = blockIdx.x * 256 + threadIdx.x;
    unsigned char r = 0;
    if (mask[i]          > 0.5f) r |= 1;
    if (mask[LL + i]     > 0.5f) r |= 2;
    if (mask[2 * LL + i] > 0.5f) r |= 4;
    if (mask[3 * LL + i] > 0.5f) r |= 8;
    mb[i] = r;
}

// ---------------- V^T bf16 hi/lo: [bh][d][l] from vh [b][l][h*64+d] ----------------
__global__ __launch_bounds__(256)
void vt_kernel(const float* __restrict__ vh, unsigned short* __restrict__ vt) {
    __shared__ float ts[64][65];
    int bh = blockIdx.x, b = bh >> 3, h = bh & 7, k0 = blockIdx.y << 6;
    int tid = threadIdx.x;
    int d = tid & 63, kr = tid >> 6;
    #pragma unroll
    for (int i = 0; i < 16; i++) {
        int k = kr + (i << 2);
        ts[k][d] = vh[((size_t)b * L_SEQ + k0 + k) * D_MODEL + h * 64 + d];
    }
    __syncthreads();
    int k = tid & 63, dr = tid >> 6;
    #pragma unroll
    for (int i = 0; i < 16; i++) {
        int dd = dr + (i << 2);
        float v = ts[k][dd];
        __nv_bfloat16 hb = __float2bfloat16(v);
        float lof = v - __bfloat162float(hb);
        __nv_bfloat16 lb = __float2bfloat16(lof);
        size_t o = ((size_t)bh * 64 + dd) * L_SEQ + k0 + k;
        vt[o]            = __bfloat16_as_ushort(hb);
        vt[VT_PLANE + o] = __bfloat16_as_ushort(lb);
    }
}

// ---------------- 128x128 SGEMM (FFMA2), modes ----------------
#define GM_PROJ 0
#define GM_ATTN 2
#define GM_FC   3
#define KT 32

template <int MODE>
__global__ __launch_bounds__(256, 2)
void gemm128(const float* __restrict__ A0, const float* __restrict__ W0,
             float* __restrict__ C0, int K, int lda, int ldb, int ldc,
             const float* __restrict__ bias, const float* __restrict__ resid,
             unsigned short* __restrict__ EH, unsigned short* __restrict__ EL,
             const float* __restrict__ A1, const float* __restrict__ W1, float* __restrict__ C1,
             const float* __restrict__ A2, const float* __restrict__ W2, float* __restrict__ C2) {
    __shared__ float As[KT][132];
    __shared__ float Bs[KT][132];

    int tid = threadIdx.x;
    int tx = tid & 15, ty = tid >> 4;
    int m0 = blockIdx.y << 7, n0 = blockIdx.x << 7;

    const float* A = A0; const float* W = W0; float* C = C0;
    float scale = 1.0f;
    if (MODE == GM_PROJ) {
        int z = blockIdx.z;
        if (z == 0)      { scale = INV_TEMP; }
        else if (z == 1) { A = A1; W = W1; C = C1; }
        else             { A = A2; W = W2; C = C2; }
    }
    if (MODE == GM_ATTN) {
        int z = blockIdx.z;
        size_t off = (size_t)(z >> 3) * L_SEQ * D_MODEL + (size_t)(z & 7) * 64;
        A += off; W += off;
        C += (size_t)z * LL;
        EH += (size_t)z * LL;
        EL += (size_t)z * LL;
    }

    int alr = tid >> 1, ak0 = (tid & 1) << 4;
    const float* arow = A + (size_t)(m0 + alr) * lda + ak0;
    const float* brow = W + (size_t)(n0 + alr) * ldb + ak0;

    unsigned long long acc[8][4];
    #pragma unroll
    for (int i = 0; i < 8; i++)
        #pragma unroll
        for (int j = 0; j < 4; j++) acc[i][j] = 0ull;

    for (int k0 = 0; k0 < K; k0 += KT) {
        float4 a[4], bv[4];
        #pragma unroll
        for (int j = 0; j < 4; j++) {
            a[j]  = *reinterpret_cast<const float4*>(arow + k0 + 4 * j);
            bv[j] = *reinterpret_cast<const float4*>(brow + k0 + 4 * j);
        }
        if (k0) __syncthreads();
        #pragma unroll
        for (int j = 0; j < 4; j++) {
            As[ak0 + 4 * j + 0][alr] = a[j].x;
            As[ak0 + 4 * j + 1][alr] = a[j].y;
            As[ak0 + 4 * j + 2][alr] = a[j].z;
            As[ak0 + 4 * j + 3][alr] = a[j].w;
            Bs[ak0 + 4 * j + 0][alr] = bv[j].x;
            Bs[ak0 + 4 * j + 1][alr] = bv[j].y;
            Bs[ak0 + 4 * j + 2][alr] = bv[j].z;
            Bs[ak0 + 4 * j + 3][alr] = bv[j].w;
        }
        __syncthreads();
        #pragma unroll 16
        for (int kk = 0; kk < KT; kk++) {
            float4 x0 = *reinterpret_cast<const float4*>(&As[kk][ty << 3]);
            float4 x1 = *reinterpret_cast<const float4*>(&As[kk][(ty << 3) + 4]);
            ulonglong2 u0 = *reinterpret_cast<const ulonglong2*>(&Bs[kk][tx << 3]);
            ulonglong2 u1 = *reinterpret_cast<const ulonglong2*>(&Bs[kk][(tx << 3) + 4]);
            unsigned long long d;
            d = pk2(x0.x, x0.x); fma2(acc[0][0], d, u0.x); fma2(acc[0][1], d, u0.y); fma2(acc[0][2], d, u1.x); fma2(acc[0][3], d, u1.y);
            d = pk2(x0.y, x0.y); fma2(acc[1][0], d, u0.x); fma2(acc[1][1], d, u0.y); fma2(acc[1][2], d, u1.x); fma2(acc[1][3], d, u1.y);
            d = pk2(x0.z, x0.z); fma2(acc[2][0], d, u0.x); fma2(acc[2][1], d, u0.y); fma2(acc[2][2], d, u1.x); fma2(acc[2][3], d, u1.y);
            d = pk2(x0.w, x0.w); fma2(acc[3][0], d, u0.x); fma2(acc[3][1], d, u0.y); fma2(acc[3][2], d, u1.x); fma2(acc[3][3], d, u1.y);
            d = pk2(x1.x, x1.x); fma2(acc[4][0], d, u0.x); fma2(acc[4][1], d, u0.y); fma2(acc[4][2], d, u1.x); fma2(acc[4][3], d, u1.y);
            d = pk2(x1.y, x1.y); fma2(acc[5][0], d, u0.x); fma2(acc[5][1], d, u0.y); fma2(acc[5][2], d, u1.x); fma2(acc[5][3], d, u1.y);
            d = pk2(x1.z, x1.z); fma2(acc[6][0], d, u0.x); fma2(acc[6][1], d, u0.y); fma2(acc[6][2], d, u1.x); fma2(acc[6][3], d, u1.y);
            d = pk2(x1.w, x1.w); fma2(acc[7][0], d, u0.x); fma2(acc[7][1], d, u0.y); fma2(acc[7][2], d, u1.x); fma2(acc[7][3], d, u1.y);
        }
    }

    #pragma unroll
    for (int i = 0; i < 8; i++) {
        int row = m0 + (ty << 3) + i;
        int col = n0 + (tx << 3);
        float2 c0 = upk2(acc[i][0]);
        float2 c1 = upk2(acc[i][1]);
        float2 c2 = upk2(acc[i][2]);
        float2 c3 = upk2(acc[i][3]);
        float4 r0 = make_float4(c0.x, c0.y, c1.x, c1.y);
        float4 r1 = make_float4(c2.x, c2.y, c3.x, c3.y);
        if (MODE == GM_PROJ) {
            r0.x *= scale; r0.y *= scale; r0.z *= scale; r0.w *= scale;
            r1.x *= scale; r1.y *= scale; r1.z *= scale; r1.w *= scale;
        }
        if (MODE == GM_FC) {
            float4 b0 = *reinterpret_cast<const float4*>(bias + col);
            float4 b1 = *reinterpret_cast<const float4*>(bias + col + 4);
            const float* rp = resid + (size_t)(row & (N_B * L_SEQ - 1)) * D_MODEL + col;
            float4 v0 = *reinterpret_cast<const float4*>(rp);
            float4 v1 = *reinterpret_cast<const float4*>(rp + 4);
            r0.x += b0.x + v0.x; r0.y += b0.y + v0.y; r0.z += b0.z + v0.z; r0.w += b0.w + v0.w;
            r1.x += b1.x + v1.x; r1.y += b1.y + v1.y; r1.z += b1.z + v1.z; r1.w += b1.w + v1.w;
        }
        float* cp = C + (size_t)row * ldc + col;
        *reinterpret_cast<float4*>(cp)     = r0;
        *reinterpret_cast<float4*>(cp + 4) = r1;
        if (MODE == GM_ATTN) {
            float e0 = __expf(r0.x), e1 = __expf(r0.y), e2 = __expf(r0.z), e3 = __expf(r0.w);
            float e4 = __expf(r1.x), e5 = __expf(r1.y), e6 = __expf(r1.z), e7 = __expf(r1.w);
            __nv_bfloat162 h01 = __float22bfloat162_rn(make_float2(e0, e1));
            __nv_bfloat162 h23 = __float22bfloat162_rn(make_float2(e2, e3));
            __nv_bfloat162 h45 = __float22bfloat162_rn(make_float2(e4, e5));
            __nv_bfloat162 h67 = __float22bfloat162_rn(make_float2(e6, e7));
            __nv_bfloat162 l01 = __float22bfloat162_rn(make_float2(e0 - __bfloat162float(h01.x), e1 - __bfloat162float(h01.y)));
            __nv_bfloat162 l23 = __float22bfloat162_rn(make_float2(e2 - __bfloat162float(h23.x), e3 - __bfloat162float(h23.y)));
            __nv_bfloat162 l45 = __float22bfloat162_rn(make_float2(e4 - __bfloat162float(h45.x), e5 - __bfloat162float(h45.y)));
            __nv_bfloat162 l67 = __float22bfloat162_rn(make_float2(e6 - __bfloat162float(h67.x), e7 - __bfloat162float(h67.y)));
            uint4 hv, lv;
            hv.x = *reinterpret_cast<unsigned int*>(&h01);
            hv.y = *reinterpret_cast<unsigned int*>(&h23);
            hv.z = *reinterpret_cast<unsigned int*>(&h45);
            hv.w = *reinterpret_cast<unsigned int*>(&h67);
            lv.x = *reinterpret_cast<unsigned int*>(&l01);
            lv.y = *reinterpret_cast<unsigned int*>(&l23);
            lv.z = *reinterpret_cast<unsigned int*>(&l45);
            lv.w = *reinterpret_cast<unsigned int*>(&l67);
            *reinterpret_cast<uint4*>(EH + (size_t)row * L_SEQ + col) = hv;
            *reinterpret_cast<uint4*>(EL + (size_t)row * L_SEQ + col) = lv;
        }
    }
}

// ---------------- warp-MMA PV: out_p = (E o M_p) V / Z_p ----------------
// One block per (p, bh, 128-q tile); k streamed in 64-chunks.
// smem: Ehi/Elo [128 q][64 k] bf16 (128B rows, SW128), Vhi/Vlo [64 n][64 k] bf16.
// 8 warps in 4(m)x2(n) grid, 32x32 warp tile, mma.sync m16n8k16 bf16,
// 3-product split: AhiBhi + AhiBlo + AloBhi.
#define PV_EHI 0
#define PV_ELO 16384
#define PV_VHI 32768
#define PV_VLO 40960
#define PV_ZS  49152
#define PV_SM_TOTAL (PV_ZS + 512)

__global__ __launch_bounds__(256, 2)
void pv_wmma(const unsigned short* __restrict__ ehi, const unsigned short* __restrict__ elo,
             const unsigned char* __restrict__ mb, const unsigned short* __restrict__ vt,
             float* __restrict__ ho) {
    extern __shared__ char smem[];
    uint32_t sbase = smem_u32(smem);
    int tid = threadIdx.x;
    int wid = tid >> 5, lane = tid & 31;

    int q0 = blockIdx.x << 7;
    int bh = blockIdx.y, bb = bh >> 3, hh = bh & 7;
    int p = blockIdx.z;

    // E-side mapping: 2 threads per q row, 32 k each
    int cq  = tid >> 1;
    int ckh = (tid & 1) << 5;
    const unsigned short* ehp = ehi + (size_t)bh * LL + (size_t)(q0 + cq) * L_SEQ + ckh;
    const unsigned short* elp = elo + (size_t)bh * LL + (size_t)(q0 + cq) * L_SEQ + ckh;
    const unsigned char*  mbp = mb + (size_t)(q0 + cq) * L_SEQ + ckh;
    uint32_t ebase = (uint32_t)cq * 128 + ((uint32_t)ckh << 1);

    // V-side mapping: rows are n (0..63), hi plane then lo plane
    int rp = tid >> 1;
    int bplane = rp >> 6, brow = rp & 63, bhalf = tid & 1;
    const unsigned short* vsrc = vt + (size_t)bplane * VT_PLANE
                                    + ((size_t)bh * 64 + brow) * L_SEQ + bhalf * 32;
    uint32_t vdst = sbase + (bplane ? PV_VLO : PV_VHI);
    uint32_t vbase = (uint32_t)brow * 128 + (uint32_t)bhalf * 64;

    // warp tile
    int wm = (wid >> 1) << 5;   // 0,32,64,96
    int wn = (wid & 1) << 5;    // 0,32

    // ldmatrix lane addresses (byte offsets before swizzle)
    // A frags (m16k16): row = wm + mf*16 + ((l>>3)&1)*8 + (l&7); colb = ks*32 + ((l>>4)&1)*16
    uint32_t a_row_off = (uint32_t)(((lane >> 3) & 1) * 8 + (lane & 7)) * 128;
    uint32_t a_col     = (uint32_t)((lane >> 4) & 1) * 16;
    // B frags (n16k16 from [n][k]): row = wn + nf2*16 + ((l>>4)&1)*8 + (l&7); colb = ks*32 + ((l>>3)&1)*16
    uint32_t b_row_off = (uint32_t)(((lane >> 4) & 1) * 8 + (lane & 7)) * 128;
    uint32_t b_col     = (uint32_t)((lane >> 3) & 1) * 16;

    float acc[2][4][4];
    #pragma unroll
    for (int i = 0; i < 2; i++)
        #pragma unroll
        for (int j = 0; j < 4; j++)
            #pragma unroll
            for (int r = 0; r < 4; r++) acc[i][j][r] = 0.0f;
    float zacc = 0.0f;

    for (int ct = 0; ct < 16; ct++) {
        int kb = ct << 6;
        if (ct) __syncthreads();

        // ---- E chunk: load hi/lo, mask, Z, swizzled stores ----
        {
            uint32_t hw[16], lw[16];
            const uint4* hs = reinterpret_cast<const uint4*>(ehp + kb);
            const uint4* ls = reinterpret_cast<const uint4*>(elp + kb);
            #pragma unroll
            for (int j = 0; j < 4; j++) {
                uint4 t = hs[j];
                hw[4 * j] = t.x; hw[4 * j + 1] = t.y; hw[4 * j + 2] = t.z; hw[4 * j + 3] = t.w;
                t = ls[j];
                lw[4 * j] = t.x; lw[4 * j + 1] = t.y; lw[4 * j + 2] = t.z; lw[4 * j + 3] = t.w;
            }
            union { uint4 v[2]; unsigned char c[32]; } mu;
            const uint4* ms = reinterpret_cast<const uint4*>(mbp + kb);
            mu.v[0] = ms[0]; mu.v[1] = ms[1];
            float z = 0.0f;
            #pragma unroll
            for (int e = 0; e < 16; e++) {
                uint32_t sel = (((mu.c[2 * e] >> p) & 1) ? 0x0000FFFFu : 0u)
                             | (((mu.c[2 * e + 1] >> p) & 1) ? 0xFFFF0000u : 0u);
                uint32_t h = hw[e] & sel, l = lw[e] & sel;
                z += __uint_as_float(h << 16) + __uint_as_float(h & 0xFFFF0000u)
                   + __uint_as_float(l << 16) + __uint_as_float(l & 0xFFFF0000u);
                hw[e] = h; lw[e] = l;
            }
            zacc += z;
            #pragma unroll
            for (int j = 0; j < 4; j++) {
                uint32_t sw = SW128(ebase + j * 16);
                STS128(sbase + PV_EHI + sw, hw[4 * j], hw[4 * j + 1], hw[4 * j + 2], hw[4 * j + 3]);
                STS128(sbase + PV_ELO + sw, lw[4 * j], lw[4 * j + 1], lw[4 * j + 2], lw[4 * j + 3]);
            }
        }
        // ---- V chunk ----
        {
            const uint4* vs = reinterpret_cast<const uint4*>(vsrc + kb);
            #pragma unroll
            for (int j = 0; j < 4; j++) {
                uint4 t = vs[j];
                uint32_t sw = SW128(vbase + j * 16);
                STS128(vdst + sw, t.x, t.y, t.z, t.w);
            }
        }
        __syncthreads();

        // ---- warp MMA over 4 k16 steps ----
        #pragma unroll
        for (int ks = 0; ks < 4; ks++) {
            uint32_t kcol = (uint32_t)ks * 32;
            uint32_t ah[2][4], al[2][4], bhf[2][4], blf[2][4];
            #pragma unroll
            for (int mf = 0; mf < 2; mf++) {
                uint32_t off = SW128((uint32_t)(wm + mf * 16) * 128 + a_row_off + kcol + a_col);
                ldm_x4(ah[mf], sbase + PV_EHI + off);
                ldm_x4(al[mf], sbase + PV_ELO + off);
            }
            #pragma unroll
            for (int nf2 = 0; nf2 < 2; nf2++) {
                uint32_t off = SW128((uint32_t)(wn + nf2 * 16) * 128 + b_row_off + kcol + b_col);
                ldm_x4(bhf[nf2], sbase + PV_VHI + off);
                ldm_x4(blf[nf2], sbase + PV_VLO + off);
            }
            #pragma unroll
            for (int mf = 0; mf < 2; mf++) {
                #pragma unroll
                for (int nf2 = 0; nf2 < 2; nf2++) {
                    #pragma unroll
                    for (int half = 0; half < 2; half++) {
                        int nf = nf2 * 2 + half;
                        const uint32_t* bh2 = &bhf[nf2][half * 2];
                        const uint32_t* bl2 = &blf[nf2][half * 2];
                        mma16816(acc[mf][nf], ah[mf], bh2);
                        mma16816(acc[mf][nf], ah[mf], bl2);
                        mma16816(acc[mf][nf], al[mf], bh2);
                    }
                }
            }
        }
    }

    // Z finalize: thread pair shares row cq
    float z2 = zacc + __shfl_xor_sync(0xffffffffu, zacc, 1);
    float* zs = reinterpret_cast<float*>(smem + PV_ZS);
    if ((tid & 1) == 0) zs[cq] = z2;
    __syncthreads();

    // epilogue: divide by Z, store
    float* hop = ho + ((size_t)(p * N_B + bb) * L_SEQ + q0) * D_MODEL + hh * 64;
    #pragma unroll
    for (int mf = 0; mf < 2; mf++) {
        int r0 = wm + mf * 16 + (lane >> 2);
        int r1 = r0 + 8;
        float zi0 = 1.0f / zs[r0];
        float zi1 = 1.0f / zs[r1];
        #pragma unroll
        for (int nf = 0; nf < 4; nf++) {
            int c = wn + nf * 8 + ((lane & 3) << 1);
            float2 v0 = make_float2(acc[mf][nf][0] * zi0, acc[mf][nf][1] * zi0);
            float2 v1 = make_float2(acc[mf][nf][2] * zi1, acc[mf][nf][3] * zi1);
            *reinterpret_cast<float2*>(hop + (size_t)r0 * D_MODEL + c) = v0;
            *reinterpret_cast<float2*>(hop + (size_t)r1 * D_MODEL + c) = v1;
        }
    }
}

// ---------------- launch ----------------
extern "C" void kernel_launch(void* const* d_in, const int* in_sizes, int n_in,
                              void* d_out, int out_size) {
    const float* q    = (const float*)d_in[0];
    const float* k    = (const float*)d_in[1];
    const float* v    = (const float*)d_in[2];
    const float* mask = (const float*)d_in[3];
    const float* w_q  = (const float*)d_in[4];
    const float* w_k  = (const float*)d_in[5];
    const float* w_v  = (const float*)d_in[6];
    const float* fc_w = (const float*)d_in[7];
    const float* fc_b = (const float*)d_in[8];
    const float* ln_g = (const float*)d_in[9];
    const float* ln_b = (const float*)d_in[10];

    float* out = (float*)d_out;

    float *qn, *qh, *kh, *vh, *ho, *attn_fb;
    unsigned short *ehi, *elo, *vt;
    unsigned char *mbp;
    cudaGetSymbolAddress((void**)&qn, g_qn);
    cudaGetSymbolAddress((void**)&qh, g_qh);
    cudaGetSymbolAddress((void**)&kh, g_kh);
    cudaGetSymbolAddress((void**)&vh, g_vh);
    cudaGetSymbolAddress((void**)&ho, g_ho);
    cudaGetSymbolAddress((void**)&attn_fb, g_attn_fallback);
    cudaGetSymbolAddress((void**)&ehi, g_ehi);
    cudaGetSymbolAddress((void**)&elo, g_elo);
    cudaGetSymbolAddress((void**)&vt, g_vt);
    cudaGetSymbolAddress((void**)&mbp, g_mb);

    float* attn_out = (out_size >= OUT_ELEMS + ATTN_ELEMS) ? out + OUT_ELEMS : attn_fb;

    cudaFuncSetAttribute(pv_wmma, cudaFuncAttributeMaxDynamicSharedMemorySize, PV_SM_TOTAL);

    // 1. pre-LN on q
    ln_kernel<<<N_B * L_SEQ, 128>>>(q, ln_g, ln_b, qn);

    // 2. q/k/v projections (q-proj folds 1/sqrt(dk))
    dim3 gproj(D_MODEL / 128, (N_B * L_SEQ) / 128, 3);
    gemm128<GM_PROJ><<<gproj, 256>>>(qn, w_q, qh, D_MODEL, D_MODEL, D_MODEL, D_MODEL,
                                     nullptr, nullptr, nullptr, nullptr,
                                     k, w_k, kh, v, w_v, vh);

    // 3. pack masks into bits
    maskpack_kernel<<<LL / 256, 256>>>(mask, mbp);

    // 4. scores S (attn output) + E split into bf16 hi/lo planes
    dim3 gattn(L_SEQ / 128, L_SEQ / 128, N_BH);
    gemm128<GM_ATTN><<<gattn, 256>>>(qh, kh, attn_out, 64, D_MODEL, D_MODEL, L_SEQ,
                                     nullptr, nullptr, ehi, elo,
                                     nullptr, nullptr, nullptr, nullptr, nullptr, nullptr);

    // 5. V^T bf16 hi/lo
    dim3 gvt(N_BH, L_SEQ / 64);
    vt_kernel<<<gvt, 256>>>(vh, vt);

    // 6. tensor-pipe PV for all P masks (mma.sync bf16, 3-product split)
    dim3 gpv(L_SEQ / 128, N_BH, N_P);
    pv_wmma<<<gpv, 256, PV_SM_TOTAL>>>(ehi, elo, mbp, vt, ho);

    // 7. FC + bias + residual
    dim3 gfc(D_MODEL / 128, (N_P * N_B * L_SEQ) / 128, 1);
    gemm128<GM_FC><<<gfc, 256>>>(ho, fc_w, out, D_MODEL, D_MODEL, D_MODEL, D_MODEL,
                                 fc_b, q, nullptr, nullptr,
                                 nullptr, nullptr, nullptr, nullptr, nullptr, nullptr);
}

// round 17
// speedup vs baseline: 3.8161x; 1.3766x over previous
#include <cstdint>
#include <cstddef>
#include <cuda_runtime.h>
#include <cuda_bf16.h>

// ---------------- problem dims ----------------
#define L_SEQ   1024
#define LL      (L_SEQ * L_SEQ)
#define D_MODEL 512
#define N_B     2
#define N_H     8
#define N_BH    (N_B * N_H)
#define N_P     4
#define INV_TEMP 0.125f
#define LN_EPS   1e-6f

#define OUT_ELEMS  (N_P * N_B * L_SEQ * D_MODEL)
#define ATTN_ELEMS (N_BH * LL)
#define VT_PLANE   (N_BH * 64 * L_SEQ)
#define HSLICE     (N_B * L_SEQ * D_MODEL)     // 1,048,576 (one [2048][512] slice)
#define WSLICE     (D_MODEL * D_MODEL)         // 262,144

typedef unsigned short u16;

// ---------------- device scratch ----------------
__device__ float g_attn_fallback[ATTN_ELEMS];
__device__ u16 g_xh[3 * HSLICE];     // inputs as bf16 hi planes: [qn | k | v]
__device__ u16 g_xl[3 * HSLICE];     // lo planes
__device__ u16 g_wh[3 * WSLICE];     // weights hi: [wq | wk | wv]
__device__ u16 g_wl[3 * WSLICE];
__device__ u16 g_fwh[WSLICE];        // fc_w hi / lo
__device__ u16 g_fwl[WSLICE];
__device__ u16 g_hh[3 * HSLICE];     // projections hi: [qh | kh | vh]
__device__ u16 g_hl[3 * HSLICE];
__device__ u16 g_ehi[ATTN_ELEMS];    // bf16 hi of exp(S)
__device__ u16 g_elo[ATTN_ELEMS];
__device__ u16 g_vt[2 * VT_PLANE];   // V^T hi plane then lo plane
__device__ u16 g_hoh[N_P * N_B * L_SEQ * D_MODEL];  // PV output hi/lo planes
__device__ u16 g_hol[N_P * N_B * L_SEQ * D_MODEL];
__device__ unsigned char g_mb[LL];   // 4 mask bits per (q,k)

// ---------------- warp MMA helpers ----------------
__device__ __forceinline__ uint32_t smem_u32(const void* p) {
    uint32_t a;
    asm("{ .reg .u64 t; cvta.to.shared.u64 t, %1; cvt.u32.u64 %0, t; }" : "=r"(a) : "l"(p));
    return a;
}
__device__ __forceinline__ void ldm_x4(uint32_t* r, uint32_t addr) {
    asm volatile("ldmatrix.sync.aligned.m8n8.x4.shared.b16 {%0,%1,%2,%3}, [%4];"
                 : "=r"(r[0]), "=r"(r[1]), "=r"(r[2]), "=r"(r[3]) : "r"(addr));
}
__device__ __forceinline__ void mma16816(float* c, const uint32_t* a, const uint32_t* b) {
    asm volatile("mma.sync.aligned.m16n8k16.row.col.f32.bf16.bf16.f32 "
                 "{%0,%1,%2,%3}, {%4,%5,%6,%7}, {%8,%9}, {%0,%1,%2,%3};"
                 : "+f"(c[0]), "+f"(c[1]), "+f"(c[2]), "+f"(c[3])
                 : "r"(a[0]), "r"(a[1]), "r"(a[2]), "r"(a[3]), "r"(b[0]), "r"(b[1]));
}

#define SW128(o) ((o) ^ (((o) >> 3) & 0x70))
#define STS128(a, x, y, z, w) asm volatile("st.shared.v4.b32 [%0], {%1,%2,%3,%4};" :: "r"(a), "r"(x), "r"(y), "r"(z), "r"(w) : "memory")

__device__ __forceinline__ u16 bfh(float v) {
    return __bfloat16_as_ushort(__float2bfloat16(v));
}
__device__ __forceinline__ void split2(float v, u16& h, u16& l) {
    __nv_bfloat16 hb = __float2bfloat16(v);
    h = __bfloat16_as_ushort(hb);
    l = bfh(v - __bfloat162float(hb));
}

// ---------------- LayerNorm -> bf16 hi/lo planes ----------------
__global__ __launch_bounds__(128)
void ln_kernel(const float* __restrict__ q, const float* __restrict__ g,
               const float* __restrict__ b, u16* __restrict__ oh, u16* __restrict__ ol) {
    int row = blockIdx.x;
    const float* x = q + (size_t)row * D_MODEL;
    int tid = threadIdx.x;
    float4 v = reinterpret_cast<const float4*>(x)[tid];
    float s  = v.x + v.y + v.z + v.w;
    float s2 = v.x * v.x + v.y * v.y + v.z * v.z + v.w * v.w;
    #pragma unroll
    for (int o = 16; o > 0; o >>= 1) {
        s  += __shfl_xor_sync(0xffffffffu, s,  o);
        s2 += __shfl_xor_sync(0xffffffffu, s2, o);
    }
    __shared__ float shs[4], shs2[4];
    __shared__ float sh_mu, sh_rs;
    int w = tid >> 5;
    if ((tid & 31) == 0) { shs[w] = s; shs2[w] = s2; }
    __syncthreads();
    if (tid == 0) {
        float S  = shs[0] + shs[1] + shs[2] + shs[3];
        float S2 = shs2[0] + shs2[1] + shs2[2] + shs2[3];
        float mu = S * (1.0f / D_MODEL);
        float var = S2 * (1.0f / D_MODEL) - mu * mu;
        sh_mu = mu;
        sh_rs = rsqrtf(var + LN_EPS);
    }
    __syncthreads();
    float mu = sh_mu, rs = sh_rs;
    float4 gv = reinterpret_cast<const float4*>(g)[tid];
    float4 bv = reinterpret_cast<const float4*>(b)[tid];
    float o0 = (v.x - mu) * rs * gv.x + bv.x;
    float o1 = (v.y - mu) * rs * gv.y + bv.y;
    float o2 = (v.z - mu) * rs * gv.z + bv.z;
    float o3 = (v.w - mu) * rs * gv.w + bv.w;
    u16 h0, l0, h1, l1, h2, l2, h3, l3;
    split2(o0, h0, l0); split2(o1, h1, l1); split2(o2, h2, l2); split2(o3, h3, l3);
    uint2 hp, lp;
    hp.x = (uint32_t)h0 | ((uint32_t)h1 << 16);
    hp.y = (uint32_t)h2 | ((uint32_t)h3 << 16);
    lp.x = (uint32_t)l0 | ((uint32_t)l1 << 16);
    lp.y = (uint32_t)l2 | ((uint32_t)l3 << 16);
    size_t o = (size_t)row * D_MODEL + tid * 4;
    *reinterpret_cast<uint2*>(oh + o) = hp;
    *reinterpret_cast<uint2*>(ol + o) = lp;
}

// ---------------- fp32 -> bf16 hi/lo planes ----------------
__global__ __launch_bounds__(256)
void cvt_kernel(const float* __restrict__ x, u16* __restrict__ oh, u16* __restrict__ ol) {
    size_t i = ((size_t)blockIdx.x * 256 + threadIdx.x) * 4;
    float4 v = *reinterpret_cast<const float4*>(x + i);
    u16 h0, l0, h1, l1, h2, l2, h3, l3;
    split2(v.x, h0, l0); split2(v.y, h1, l1); split2(v.z, h2, l2); split2(v.w, h3, l3);
    uint2 hp, lp;
    hp.x = (uint32_t)h0 | ((uint32_t)h1 << 16);
    hp.y = (uint32_t)h2 | ((uint32_t)h3 << 16);
    lp.x = (uint32_t)l0 | ((uint32_t)l1 << 16);
    lp.y = (uint32_t)l2 | ((uint32_t)l3 << 16);
    *reinterpret_cast<uint2*>(oh + i) = hp;
    *reinterpret_cast<uint2*>(ol + i) = lp;
}

// ---------------- mask pack: 4 fp32 masks -> 4 bits/byte ----------------
__global__ __launch_bounds__(256)
void maskpack_kernel(const float* __restrict__ mask, unsigned char* __restrict__ mb) {
    int i = blockIdx.x * 256 + threadIdx.x;
    unsigned char r = 0;
    if (mask[i]          > 0.5f) r |= 1;
    if (mask[LL + i]     > 0.5f) r |= 2;
    if (mask[2 * LL + i] > 0.5f) r |= 4;
    if (mask[3 * LL + i] > 0.5f) r |= 8;
    mb[i] = r;
}

// ---------------- V^T planes: [bh][d][l] from vh planes [b*l][h*64+d] ----------------
__global__ __launch_bounds__(256)
void vt_kernel(const u16* __restrict__ vhh, const u16* __restrict__ vhl,
               u16* __restrict__ vt) {
    __shared__ u16 th[64][66];
    __shared__ u16 tl[64][66];
    int bh = blockIdx.x, b = bh >> 3, h = bh & 7, k0 = blockIdx.y << 6;
    int tid = threadIdx.x;
    int d = tid & 63, kr = tid >> 6;
    #pragma unroll
    for (int i = 0; i < 16; i++) {
        int k = kr + (i << 2);
        size_t src = ((size_t)(b * L_SEQ + k0 + k)) * D_MODEL + h * 64 + d;
        th[k][d] = vhh[src];
        tl[k][d] = vhl[src];
    }
    __syncthreads();
    int k = tid & 63, dr = tid >> 6;
    #pragma unroll
    for (int i = 0; i < 16; i++) {
        int dd = dr + (i << 2);
        size_t o = ((size_t)bh * 64 + dd) * L_SEQ + k0 + k;
        vt[o]            = th[k][dd];
        vt[VT_PLANE + o] = tl[k][dd];
    }
}

// ---------------- generic split-bf16 mma.sync GEMM: C = A * B^T ----------------
// A [M][K], B [N][K], both as bf16 hi/lo planes with row stride 512.
// 128x128 tile, KT=64 chunk, 8 warps at 32m x 64n, 3-product split.
#define HG_PROJ 0
#define HG_QK   1
#define HG_FC   2
#define HG_SMEM 65536
// smem layout: AHI 16K | ALO 16K | BHI 16K | BLO 16K

template <int MODE>
__global__ __launch_bounds__(256, 2)
void hgemm(const u16* __restrict__ Ah, const u16* __restrict__ Al,
           const u16* __restrict__ Bh, const u16* __restrict__ Bl,
           int K,
           u16* __restrict__ Ch, u16* __restrict__ Cl,          // PROJ
           float* __restrict__ S, u16* __restrict__ EH, u16* __restrict__ EL,  // QK
           float* __restrict__ OUT, const float* __restrict__ bias,
           const float* __restrict__ resid) {                    // FC
    extern __shared__ char smem[];
    uint32_t sb = smem_u32(smem);
    const uint32_t S_AHI = 0, S_ALO = 16384, S_BHI = 32768, S_BLO = 49152;

    int tid = threadIdx.x;
    int wid = tid >> 5, lane = tid & 31;
    int m0 = blockIdx.y << 7, n0 = blockIdx.x << 7;

    float scale = 1.0f;
    if (MODE == HG_PROJ) {
        int z = blockIdx.z;
        Ah += (size_t)z * HSLICE; Al += (size_t)z * HSLICE;
        Bh += (size_t)z * WSLICE; Bl += (size_t)z * WSLICE;
        Ch += (size_t)z * HSLICE; Cl += (size_t)z * HSLICE;
        if (z == 0) scale = INV_TEMP;
    }
    if (MODE == HG_QK) {
        int z = blockIdx.z, b = z >> 3, h = z & 7;
        size_t off = (size_t)b * L_SEQ * D_MODEL + (size_t)h * 64;
        Ah += off; Al += off; Bh += off; Bl += off;
        S  += (size_t)z * LL;
        EH += (size_t)z * LL;
        EL += (size_t)z * LL;
    }

    // chunk loaders: 2 threads per row, 32 k (64B) each
    int row = tid >> 1, half = tid & 1;
    const u16* ahp = Ah + (size_t)(m0 + row) * D_MODEL + half * 32;
    const u16* alp = Al + (size_t)(m0 + row) * D_MODEL + half * 32;
    const u16* bhp = Bh + (size_t)(n0 + row) * D_MODEL + half * 32;
    const u16* blp = Bl + (size_t)(n0 + row) * D_MODEL + half * 32;
    uint32_t adst = (uint32_t)row * 128 + (uint32_t)half * 64;

    // warp tile 32m x 64n
    int wm = (wid >> 1) << 5;   // 0,32,64,96
    int wn = (wid & 1) << 6;    // 0,64
    uint32_t a_row_off = (uint32_t)(((lane >> 3) & 1) * 8 + (lane & 7)) * 128;
    uint32_t a_col     = (uint32_t)((lane >> 4) & 1) * 16;
    uint32_t b_row_off = (uint32_t)(((lane >> 4) & 1) * 8 + (lane & 7)) * 128;
    uint32_t b_col     = (uint32_t)((lane >> 3) & 1) * 16;

    float acc[2][8][4];
    #pragma unroll
    for (int i = 0; i < 2; i++)
        #pragma unroll
        for (int j = 0; j < 8; j++)
            #pragma unroll
            for (int r = 0; r < 4; r++) acc[i][j][r] = 0.0f;

    for (int k0 = 0; k0 < K; k0 += 64) {
        if (k0) __syncthreads();
        #pragma unroll
        for (int j = 0; j < 4; j++) {
            uint32_t sw = SW128(adst + j * 16);
            uint4 t = *reinterpret_cast<const uint4*>(ahp + k0 + j * 8);
            STS128(sb + S_AHI + sw, t.x, t.y, t.z, t.w);
            t = *reinterpret_cast<const uint4*>(alp + k0 + j * 8);
            STS128(sb + S_ALO + sw, t.x, t.y, t.z, t.w);
            t = *reinterpret_cast<const uint4*>(bhp + k0 + j * 8);
            STS128(sb + S_BHI + sw, t.x, t.y, t.z, t.w);
            t = *reinterpret_cast<const uint4*>(blp + k0 + j * 8);
            STS128(sb + S_BLO + sw, t.x, t.y, t.z, t.w);
        }
        __syncthreads();
        #pragma unroll
        for (int ks = 0; ks < 4; ks++) {
            uint32_t kcol = (uint32_t)ks * 32;
            uint32_t ah[2][4], al[2][4];
            #pragma unroll
            for (int mf = 0; mf < 2; mf++) {
                uint32_t off = SW128((uint32_t)(wm + mf * 16) * 128 + a_row_off + kcol + a_col);
                ldm_x4(ah[mf], sb + S_AHI + off);
                ldm_x4(al[mf], sb + S_ALO + off);
            }
            #pragma unroll
            for (int hn = 0; hn < 2; hn++) {
                uint32_t bh2[2][4], bl2[2][4];
                #pragma unroll
                for (int nf2 = 0; nf2 < 2; nf2++) {
                    uint32_t off = SW128((uint32_t)(wn + hn * 32 + nf2 * 16) * 128 + b_row_off + kcol + b_col);
                    ldm_x4(bh2[nf2], sb + S_BHI + off);
                    ldm_x4(bl2[nf2], sb + S_BLO + off);
                }
                #pragma unroll
                for (int mf = 0; mf < 2; mf++) {
                    #pragma unroll
                    for (int nf2 = 0; nf2 < 2; nf2++) {
                        #pragma unroll
                        for (int hb = 0; hb < 2; hb++) {
                            int ai = hn * 4 + nf2 * 2 + hb;
                            const uint32_t* bhr = &bh2[nf2][hb * 2];
                            const uint32_t* blr = &bl2[nf2][hb * 2];
                            mma16816(acc[mf][ai], ah[mf], bhr);
                            mma16816(acc[mf][ai], ah[mf], blr);
                            mma16816(acc[mf][ai], al[mf], bhr);
                        }
                    }
                }
            }
        }
    }

    // ---------------- epilogue ----------------
    #pragma unroll
    for (int mf = 0; mf < 2; mf++) {
        int r0 = wm + mf * 16 + (lane >> 2);
        #pragma unroll
        for (int nf = 0; nf < 8; nf++) {
            int c = wn + nf * 8 + ((lane & 3) << 1);
            const float* a4 = acc[mf][nf];
            #pragma unroll
            for (int rr = 0; rr < 2; rr++) {
                int r = r0 + rr * 8;
                float v0 = a4[rr * 2], v1 = a4[rr * 2 + 1];
                if (MODE == HG_PROJ) {
                    v0 *= scale; v1 *= scale;
                    u16 h0, l0, h1, l1;
                    split2(v0, h0, l0); split2(v1, h1, l1);
                    size_t o = (size_t)(m0 + r) * D_MODEL + n0 + c;
                    *reinterpret_cast<ushort2*>(Ch + o) = make_ushort2(h0, h1);
                    *reinterpret_cast<ushort2*>(Cl + o) = make_ushort2(l0, l1);
                }
                if (MODE == HG_QK) {
                    size_t o = (size_t)(m0 + r) * L_SEQ + n0 + c;
                    *reinterpret_cast<float2*>(S + o) = make_float2(v0, v1);
                    float e0 = __expf(v0), e1 = __expf(v1);
                    u16 h0, l0, h1, l1;
                    split2(e0, h0, l0); split2(e1, h1, l1);
                    *reinterpret_cast<ushort2*>(EH + o) = make_ushort2(h0, h1);
                    *reinterpret_cast<ushort2*>(EL + o) = make_ushort2(l0, l1);
                }
                if (MODE == HG_FC) {
                    int rowm = m0 + r;
                    float2 bb = *reinterpret_cast<const float2*>(bias + n0 + c);
                    const float* rp = resid + (size_t)(rowm & (N_B * L_SEQ - 1)) * D_MODEL + n0 + c;
                    float2 rv = *reinterpret_cast<const float2*>(rp);
                    float2 ov = make_float2(v0 + bb.x + rv.x, v1 + bb.y + rv.y);
                    *reinterpret_cast<float2*>(OUT + (size_t)rowm * D_MODEL + n0 + c) = ov;
                }
            }
        }
    }
}

// ---------------- warp-MMA PV: out_p = (E o M_p) V / Z_p ----------------
#define PV_EHI 0
#define PV_ELO 16384
#define PV_VHI 32768
#define PV_VLO 40960
#define PV_ZS  49152
#define PV_SM_TOTAL (PV_ZS + 512)

__global__ __launch_bounds__(256, 2)
void pv_wmma(const u16* __restrict__ ehi, const u16* __restrict__ elo,
             const unsigned char* __restrict__ mb, const u16* __restrict__ vt,
             u16* __restrict__ hoh, u16* __restrict__ hol) {
    extern __shared__ char smem[];
    uint32_t sbase = smem_u32(smem);
    int tid = threadIdx.x;
    int wid = tid >> 5, lane = tid & 31;

    int q0 = blockIdx.x << 7;
    int bh = blockIdx.y, bb = bh >> 3, hh = bh & 7;
    int p = blockIdx.z;

    int cq  = tid >> 1;
    int ckh = (tid & 1) << 5;
    const u16* ehp = ehi + (size_t)bh * LL + (size_t)(q0 + cq) * L_SEQ + ckh;
    const u16* elp = elo + (size_t)bh * LL + (size_t)(q0 + cq) * L_SEQ + ckh;
    const unsigned char* mbp = mb + (size_t)(q0 + cq) * L_SEQ + ckh;
    uint32_t ebase = (uint32_t)cq * 128 + ((uint32_t)ckh << 1);

    int rp = tid >> 1;
    int bplane = rp >> 6, brow = rp & 63, bhalf = tid & 1;
    const u16* vsrc = vt + (size_t)bplane * VT_PLANE
                         + ((size_t)bh * 64 + brow) * L_SEQ + bhalf * 32;
    uint32_t vdst = sbase + (bplane ? PV_VLO : PV_VHI);
    uint32_t vbase = (uint32_t)brow * 128 + (uint32_t)bhalf * 64;

    int wm = (wid >> 1) << 5;
    int wn = (wid & 1) << 5;
    uint32_t a_row_off = (uint32_t)(((lane >> 3) & 1) * 8 + (lane & 7)) * 128;
    uint32_t a_col     = (uint32_t)((lane >> 4) & 1) * 16;
    uint32_t b_row_off = (uint32_t)(((lane >> 4) & 1) * 8 + (lane & 7)) * 128;
    uint32_t b_col     = (uint32_t)((lane >> 3) & 1) * 16;

    float acc[2][4][4];
    #pragma unroll
    for (int i = 0; i < 2; i++)
        #pragma unroll
        for (int j = 0; j < 4; j++)
            #pragma unroll
            for (int r = 0; r < 4; r++) acc[i][j][r] = 0.0f;
    float zacc = 0.0f;

    for (int ct = 0; ct < 16; ct++) {
        int kb = ct << 6;
        if (ct) __syncthreads();

        {
            uint32_t hw[16], lw[16];
            const uint4* hs = reinterpret_cast<const uint4*>(ehp + kb);
            const uint4* ls = reinterpret_cast<const uint4*>(elp + kb);
            #pragma unroll
            for (int j = 0; j < 4; j++) {
                uint4 t = hs[j];
                hw[4 * j] = t.x; hw[4 * j + 1] = t.y; hw[4 * j + 2] = t.z; hw[4 * j + 3] = t.w;
                t = ls[j];
                lw[4 * j] = t.x; lw[4 * j + 1] = t.y; lw[4 * j + 2] = t.z; lw[4 * j + 3] = t.w;
            }
            union { uint4 v[2]; unsigned char c[32]; } mu;
            const uint4* ms = reinterpret_cast<const uint4*>(mbp + kb);
            mu.v[0] = ms[0]; mu.v[1] = ms[1];
            float z = 0.0f;
            #pragma unroll
            for (int e = 0; e < 16; e++) {
                uint32_t sel = (((mu.c[2 * e] >> p) & 1) ? 0x0000FFFFu : 0u)
                             | (((mu.c[2 * e + 1] >> p) & 1) ? 0xFFFF0000u : 0u);
                uint32_t h = hw[e] & sel, l = lw[e] & sel;
                z += __uint_as_float(h << 16) + __uint_as_float(h & 0xFFFF0000u)
                   + __uint_as_float(l << 16) + __uint_as_float(l & 0xFFFF0000u);
                hw[e] = h; lw[e] = l;
            }
            zacc += z;
            #pragma unroll
            for (int j = 0; j < 4; j++) {
                uint32_t sw = SW128(ebase + j * 16);
                STS128(sbase + PV_EHI + sw, hw[4 * j], hw[4 * j + 1], hw[4 * j + 2], hw[4 * j + 3]);
                STS128(sbase + PV_ELO + sw, lw[4 * j], lw[4 * j + 1], lw[4 * j + 2], lw[4 * j + 3]);
            }
        }
        {
            const uint4* vs = reinterpret_cast<const uint4*>(vsrc + kb);
            #pragma unroll
            for (int j = 0; j < 4; j++) {
                uint4 t = vs[j];
                uint32_t sw = SW128(vbase + j * 16);
                STS128(vdst + sw, t.x, t.y, t.z, t.w);
            }
        }
        __syncthreads();

        #pragma unroll
        for (int ks = 0; ks < 4; ks++) {
            uint32_t kcol = (uint32_t)ks * 32;
            uint32_t ah[2][4], al[2][4], bhf[2][4], blf[2][4];
            #pragma unroll
            for (int mf = 0; mf < 2; mf++) {
                uint32_t off = SW128((uint32_t)(wm + mf * 16) * 128 + a_row_off + kcol + a_col);
                ldm_x4(ah[mf], sbase + PV_EHI + off);
                ldm_x4(al[mf], sbase + PV_ELO + off);
            }
            #pragma unroll
            for (int nf2 = 0; nf2 < 2; nf2++) {
                uint32_t off = SW128((uint32_t)(wn + nf2 * 16) * 128 + b_row_off + kcol + b_col);
                ldm_x4(bhf[nf2], sbase + PV_VHI + off);
                ldm_x4(blf[nf2], sbase + PV_VLO + off);
            }
            #pragma unroll
            for (int mf = 0; mf < 2; mf++) {
                #pragma unroll
                for (int nf2 = 0; nf2 < 2; nf2++) {
                    #pragma unroll
                    for (int half = 0; half < 2; half++) {
                        int nf = nf2 * 2 + half;
                        const uint32_t* bh2 = &bhf[nf2][half * 2];
                        const uint32_t* bl2 = &blf[nf2][half * 2];
                        mma16816(acc[mf][nf], ah[mf], bh2);
                        mma16816(acc[mf][nf], ah[mf], bl2);
                        mma16816(acc[mf][nf], al[mf], bh2);
                    }
                }
            }
        }
    }

    float z2 = zacc + __shfl_xor_sync(0xffffffffu, zacc, 1);
    float* zs = reinterpret_cast<float*>(smem + PV_ZS);
    if ((tid & 1) == 0) zs[cq] = z2;
    __syncthreads();

    size_t base = ((size_t)(p * N_B + bb) * L_SEQ + q0) * D_MODEL + hh * 64;
    #pragma unroll
    for (int mf = 0; mf < 2; mf++) {
        int r0 = wm + mf * 16 + (lane >> 2);
        int r1 = r0 + 8;
        float zi0 = 1.0f / zs[r0];
        float zi1 = 1.0f / zs[r1];
        #pragma unroll
        for (int nf = 0; nf < 4; nf++) {
            int c = wn + nf * 8 + ((lane & 3) << 1);
            float o00 = acc[mf][nf][0] * zi0, o01 = acc[mf][nf][1] * zi0;
            float o10 = acc[mf][nf][2] * zi1, o11 = acc[mf][nf][3] * zi1;
            u16 h0, l0, h1, l1;
            split2(o00, h0, l0); split2(o01, h1, l1);
            size_t oo = base + (size_t)r0 * D_MODEL + c;
            *reinterpret_cast<ushort2*>(hoh + oo) = make_ushort2(h0, h1);
            *reinterpret_cast<ushort2*>(hol + oo) = make_ushort2(l0, l1);
            split2(o10, h0, l0); split2(o11, h1, l1);
            oo = base + (size_t)r1 * D_MODEL + c;
            *reinterpret_cast<ushort2*>(hoh + oo) = make_ushort2(h0, h1);
            *reinterpret_cast<ushort2*>(hol + oo) = make_ushort2(l0, l1);
        }
    }
}

// ---------------- launch ----------------
extern "C" void kernel_launch(void* const* d_in, const int* in_sizes, int n_in,
                              void* d_out, int out_size) {
    const float* q    = (const float*)d_in[0];
    const float* k    = (const float*)d_in[1];
    const float* v    = (const float*)d_in[2];
    const float* mask = (const float*)d_in[3];
    const float* w_q  = (const float*)d_in[4];
    const float* w_k  = (const float*)d_in[5];
    const float* w_v  = (const float*)d_in[6];
    const float* fc_w = (const float*)d_in[7];
    const float* fc_b = (const float*)d_in[8];
    const float* ln_g = (const float*)d_in[9];
    const float* ln_b = (const float*)d_in[10];

    float* out = (float*)d_out;

    float *attn_fb;
    u16 *xh, *xl, *wh, *wl, *fwh, *fwl, *hhp, *hlp, *ehi, *elo, *vt, *hoh, *hol;
    unsigned char *mbp;
    cudaGetSymbolAddress((void**)&attn_fb, g_attn_fallback);
    cudaGetSymbolAddress((void**)&xh, g_xh);
    cudaGetSymbolAddress((void**)&xl, g_xl);
    cudaGetSymbolAddress((void**)&wh, g_wh);
    cudaGetSymbolAddress((void**)&wl, g_wl);
    cudaGetSymbolAddress((void**)&fwh, g_fwh);
    cudaGetSymbolAddress((void**)&fwl, g_fwl);
    cudaGetSymbolAddress((void**)&hhp, g_hh);
    cudaGetSymbolAddress((void**)&hlp, g_hl);
    cudaGetSymbolAddress((void**)&ehi, g_ehi);
    cudaGetSymbolAddress((void**)&elo, g_elo);
    cudaGetSymbolAddress((void**)&vt, g_vt);
    cudaGetSymbolAddress((void**)&hoh, g_hoh);
    cudaGetSymbolAddress((void**)&hol, g_hol);
    cudaGetSymbolAddress((void**)&mbp, g_mb);

    float* attn_out = (out_size >= OUT_ELEMS + ATTN_ELEMS) ? out + OUT_ELEMS : attn_fb;

    cudaFuncSetAttribute(hgemm<HG_PROJ>, cudaFuncAttributeMaxDynamicSharedMemorySize, HG_SMEM);
    cudaFuncSetAttribute(hgemm<HG_QK>,   cudaFuncAttributeMaxDynamicSharedMemorySize, HG_SMEM);
    cudaFuncSetAttribute(hgemm<HG_FC>,   cudaFuncAttributeMaxDynamicSharedMemorySize, HG_SMEM);
    cudaFuncSetAttribute(pv_wmma, cudaFuncAttributeMaxDynamicSharedMemorySize, PV_SM_TOTAL);

    // 1. pre-LN on q -> qn planes (slice 0 of x)
    ln_kernel<<<N_B * L_SEQ, 128>>>(q, ln_g, ln_b, xh, xl);

    // 2. split k, v inputs and all weights to bf16 planes
    cvt_kernel<<<HSLICE / 1024, 256>>>(k, xh + HSLICE, xl + HSLICE);
    cvt_kernel<<<HSLICE / 1024, 256>>>(v, xh + 2 * HSLICE, xl + 2 * HSLICE);
    cvt_kernel<<<WSLICE / 1024, 256>>>(w_q, wh, wl);
    cvt_kernel<<<WSLICE / 1024, 256>>>(w_k, wh + WSLICE, wl + WSLICE);
    cvt_kernel<<<WSLICE / 1024, 256>>>(w_v, wh + 2 * WSLICE, wl + 2 * WSLICE);
    cvt_kernel<<<WSLICE / 1024, 256>>>(fc_w, fwh, fwl);

    // 3. pack masks
    maskpack_kernel<<<LL / 256, 256>>>(mask, mbp);

    // 4. projections (z=0 q with INV_TEMP, z=1 k, z=2 v) -> qh/kh/vh planes
    dim3 gproj(D_MODEL / 128, (N_B * L_SEQ) / 128, 3);
    hgemm<HG_PROJ><<<gproj, 256, HG_SMEM>>>(xh, xl, wh, wl, D_MODEL,
                                            hhp, hlp,
                                            nullptr, nullptr, nullptr,
                                            nullptr, nullptr, nullptr);

    // 5. QK: S fp32 (attn output) + E = exp(S) hi/lo planes
    dim3 gattn(L_SEQ / 128, L_SEQ / 128, N_BH);
    hgemm<HG_QK><<<gattn, 256, HG_SMEM>>>(hhp, hlp, hhp + HSLICE, hlp + HSLICE, 64,
                                          nullptr, nullptr,
                                          attn_out, ehi, elo,
                                          nullptr, nullptr, nullptr);

    // 6. V^T planes from vh planes (slice 2)
    dim3 gvt(N_BH, L_SEQ / 64);
    vt_kernel<<<gvt, 256>>>(hhp + 2 * HSLICE, hlp + 2 * HSLICE, vt);

    // 7. PV for all P masks -> ho planes
    dim3 gpv(L_SEQ / 128, N_BH, N_P);
    pv_wmma<<<gpv, 256, PV_SM_TOTAL>>>(ehi, elo, mbp, vt, hoh, hol);

    // 8. FC + bias + residual -> out
    dim3 gfc(D_MODEL / 128, (N_P * N_B * L_SEQ) / 128, 1);
    hgemm<HG_FC><<<gfc, 256, HG_SMEM>>>(hoh, hol, fwh, fwl, D_MODEL,
                                        nullptr, nullptr,
                                        nullptr, nullptr, nullptr,
                                        out, fc_b, q);
}